// round 1
// baseline (speedup 1.0000x reference)
#include <cuda_runtime.h>

// ---------------- problem constants ----------------
constexpr int BB     = 32768;   // batch
constexpr int DD     = 128;     // input dim
constexpr int OUTF   = 192;     // n_d + n_a
constexpr int HH     = 384;     // 2*OUTF
constexpr int NSTEP  = 3;
constexpr int NCHUNK = 256;     // BB / VBS(128)
constexpr int NDOUT  = 64;      // n_d
#define EPS_BN 1e-5f

// ---------------- scratch (device globals: allocation-free) ----------------
__device__ float g_xbn[BB * DD];            // BN'd input
__device__ float g_att[BB * DD];            // att, then masked_x in place, then next att
__device__ float g_M[BB * DD];              // sparsemax mask
__device__ float g_h[BB * HH];              // GEMM output buffer
__device__ float g_a[BB * OUTF];            // GLU output / GEMM2 input / dec result
__device__ float g_enc[BB * OUTF];          // enc result
__device__ float g_bnpart[NCHUNK * 2 * DD];
__device__ float g_bnscale[DD];
__device__ float g_bnshift[DD];
__device__ float g_losspart[NSTEP * NCHUNK];

// ---------------- f32x2 packed math (Blackwell) ----------------
__device__ __forceinline__ unsigned long long pk2(float lo, float hi) {
    unsigned long long r;
    asm("mov.b64 %0, {%1,%2};" : "=l"(r) : "f"(lo), "f"(hi));
    return r;
}
__device__ __forceinline__ void up2(unsigned long long v, float& a, float& b) {
    asm("mov.b64 {%0,%1}, %2;" : "=f"(a), "=f"(b) : "l"(v));
}
__device__ __forceinline__ unsigned long long ffma2(unsigned long long a,
                                                    unsigned long long b,
                                                    unsigned long long c) {
    unsigned long long d;
    asm("fma.rn.f32x2 %0, %1, %2, %3;" : "=l"(d) : "l"(a), "l"(b), "l"(c));
    return d;
}

// ---------------- BN stats (two-pass, deterministic) ----------------
__global__ void bn_partial_kernel(const float* __restrict__ x) {
    __shared__ float ss[256], sq[256];
    int t = threadIdx.x, blk = blockIdx.x;
    int col = t & 127, half = t >> 7;
    const float* xp = x + ((size_t)blk * 128 + half * 64) * DD + col;
    float s = 0.f, q = 0.f;
#pragma unroll 8
    for (int r = 0; r < 64; r++) { float v = xp[(size_t)r * DD]; s += v; q += v * v; }
    ss[t] = s; sq[t] = q;
    __syncthreads();
    if (t < 128) {
        g_bnpart[(blk * 2 + 0) * DD + t] = ss[t] + ss[t + 128];
        g_bnpart[(blk * 2 + 1) * DD + t] = sq[t] + sq[t + 128];
    }
}

__global__ void bn_finalize_kernel(const float* __restrict__ gam, const float* __restrict__ bet) {
    int c = threadIdx.x;   // 128 threads
    float s = 0.f, q = 0.f;
    for (int b = 0; b < NCHUNK; b++) {
        s += g_bnpart[(b * 2 + 0) * DD + c];
        q += g_bnpart[(b * 2 + 1) * DD + c];
    }
    float mean = s / (float)BB;
    float var  = q / (float)BB - mean * mean;
    float inv  = 1.f / sqrtf(var + EPS_BN);
    float sc   = gam[c] * inv;
    g_bnscale[c] = sc;
    g_bnshift[c] = bet[c] - mean * sc;
}

__global__ void bn_apply_kernel(const float* __restrict__ x) {
    int i = blockIdx.x * blockDim.x + threadIdx.x;   // over BB*DD/4 float4s
    if (i >= BB * DD / 4) return;
    float4 v = ((const float4*)x)[i];
    int c = (i & 31) * 4;   // DD/4 = 32 float4s per row
    v.x = v.x * g_bnscale[c + 0] + g_bnshift[c + 0];
    v.y = v.y * g_bnscale[c + 1] + g_bnshift[c + 1];
    v.z = v.z * g_bnscale[c + 2] + g_bnshift[c + 2];
    v.w = v.w * g_bnscale[c + 3] + g_bnshift[c + 3];
    ((float4*)g_xbn)[i] = v;
    ((float4*)g_att)[i] = make_float4(1.f, 1.f, 1.f, 1.f);
}

// ---------------- sparsemax (Michelot iterative support) + mask + loss ----------------
__global__ void sparsemax_kernel(int step) {
    __shared__ float wl[8];
    int t = threadIdx.x, lane = t & 31, w = t >> 5, blk = blockIdx.x;
    float acc = 0.f;
    for (int rr = 0; rr < 16; rr++) {
        size_t row = (size_t)blk * 128 + w * 16 + rr;
        float* ap = g_att + row * DD;
        float z0 = ap[lane], z1 = ap[lane + 32], z2 = ap[lane + 64], z3 = ap[lane + 96];
        float mx = fmaxf(fmaxf(z0, z1), fmaxf(z2, z3));
#pragma unroll
        for (int o = 16; o; o >>= 1) mx = fmaxf(mx, __shfl_xor_sync(0xffffffffu, mx, o));
        z0 -= mx; z1 -= mx; z2 -= mx; z3 -= mx;
        float sm = z0 + z1 + z2 + z3;
#pragma unroll
        for (int o = 16; o; o >>= 1) sm += __shfl_xor_sync(0xffffffffu, sm, o);
        float tau = (sm - 1.f) * (1.f / 128.f);
        int cnt = 128;
        for (int it = 0; it < 64; it++) {
            float s = 0.f; int c = 0;
            if (z0 > tau) { s += z0; c++; }
            if (z1 > tau) { s += z1; c++; }
            if (z2 > tau) { s += z2; c++; }
            if (z3 > tau) { s += z3; c++; }
#pragma unroll
            for (int o = 16; o; o >>= 1) {
                s += __shfl_xor_sync(0xffffffffu, s, o);
                c += __shfl_xor_sync(0xffffffffu, c, o);
            }
            if (c == cnt) break;      // support stable -> tau is the fixed point
            cnt = c; tau = (s - 1.f) / (float)c;
        }
        const float* xp = g_xbn + row * DD;
        float* Mp = g_M + row * DD;
        float m0 = fmaxf(z0 - tau, 0.f), m1 = fmaxf(z1 - tau, 0.f);
        float m2 = fmaxf(z2 - tau, 0.f), m3 = fmaxf(z3 - tau, 0.f);
        Mp[lane] = m0; Mp[lane + 32] = m1; Mp[lane + 64] = m2; Mp[lane + 96] = m3;
        ap[lane]      = m0 * xp[lane];
        ap[lane + 32] = m1 * xp[lane + 32];
        ap[lane + 64] = m2 * xp[lane + 64];
        ap[lane + 96] = m3 * xp[lane + 96];
        float rl = m0 * logf(m0 + 1e-10f) + m1 * logf(m1 + 1e-10f)
                 + m2 * logf(m2 + 1e-10f) + m3 * logf(m3 + 1e-10f);
#pragma unroll
        for (int o = 16; o; o >>= 1) rl += __shfl_xor_sync(0xffffffffu, rl, o);
        acc += rl;
    }
    if (lane == 0) wl[w] = acc;
    __syncthreads();
    if (t == 0) {
        float s = 0.f;
        for (int i = 0; i < 8; i++) s += wl[i];
        g_losspart[step * NCHUNK + blk] = s;
    }
}

// ---------------- GEMM: C[M,384] = A[M,K] * W[384,K]^T  (fp32, packed f32x2 FFMA) ----
template <int K>
__global__ __launch_bounds__(256) void gemm_nt_kernel(const float* __restrict__ A,
                                                      const float* __restrict__ W,
                                                      float* __restrict__ C) {
    constexpr int T = K / 16;
    __shared__ __align__(16) float As[2][16][132];
    __shared__ __align__(16) float Bs[2][16][132];
    const int t  = threadIdx.x;
    const int m0 = blockIdx.y * 128, n0 = blockIdx.x * 128;
    const int tx = t & 15, ty = t >> 4;
    const int rowA = t >> 2, kq = t & 3;

    const float* Ap = A + (size_t)(m0 + rowA) * K + kq * 4;
    const float* Wp = W + (size_t)(n0 + rowA) * K + kq * 4;

    unsigned long long c2[8][4];
#pragma unroll
    for (int i = 0; i < 8; i++)
#pragma unroll
        for (int j = 0; j < 4; j++) c2[i][j] = 0ull;

    float4 ar0, ar1, br0, br1;
    ar0 = *(const float4*)(Ap);
    ar1 = *(const float4*)(Ap + 64 * K);
    br0 = *(const float4*)(Wp);
    br1 = *(const float4*)(Wp + 64 * K);
    {
        int kb = kq * 4;
        As[0][kb + 0][rowA] = ar0.x; As[0][kb + 1][rowA] = ar0.y;
        As[0][kb + 2][rowA] = ar0.z; As[0][kb + 3][rowA] = ar0.w;
        As[0][kb + 0][rowA + 64] = ar1.x; As[0][kb + 1][rowA + 64] = ar1.y;
        As[0][kb + 2][rowA + 64] = ar1.z; As[0][kb + 3][rowA + 64] = ar1.w;
        Bs[0][kb + 0][rowA] = br0.x; Bs[0][kb + 1][rowA] = br0.y;
        Bs[0][kb + 2][rowA] = br0.z; Bs[0][kb + 3][rowA] = br0.w;
        Bs[0][kb + 0][rowA + 64] = br1.x; Bs[0][kb + 1][rowA + 64] = br1.y;
        Bs[0][kb + 2][rowA + 64] = br1.z; Bs[0][kb + 3][rowA + 64] = br1.w;
    }
    __syncthreads();

    for (int kt = 0; kt < T; kt++) {
        const int buf = kt & 1;
        if (kt + 1 < T) {
            const float* Ap2 = Ap + (kt + 1) * 16;
            const float* Wp2 = Wp + (kt + 1) * 16;
            ar0 = *(const float4*)(Ap2);
            ar1 = *(const float4*)(Ap2 + 64 * K);
            br0 = *(const float4*)(Wp2);
            br1 = *(const float4*)(Wp2 + 64 * K);
        }
#pragma unroll
        for (int k = 0; k < 16; k++) {
            const float4 a0 = *(const float4*)&As[buf][k][ty * 8];
            const float4 a1 = *(const float4*)&As[buf][k][ty * 8 + 4];
            const float4 b0 = *(const float4*)&Bs[buf][k][tx * 8];
            const float4 b1 = *(const float4*)&Bs[buf][k][tx * 8 + 4];
            unsigned long long bp0 = pk2(b0.x, b0.y), bp1 = pk2(b0.z, b0.w);
            unsigned long long bp2 = pk2(b1.x, b1.y), bp3 = pk2(b1.z, b1.w);
            float am[8] = {a0.x, a0.y, a0.z, a0.w, a1.x, a1.y, a1.z, a1.w};
#pragma unroll
            for (int i = 0; i < 8; i++) {
                unsigned long long ad = pk2(am[i], am[i]);
                c2[i][0] = ffma2(ad, bp0, c2[i][0]);
                c2[i][1] = ffma2(ad, bp1, c2[i][1]);
                c2[i][2] = ffma2(ad, bp2, c2[i][2]);
                c2[i][3] = ffma2(ad, bp3, c2[i][3]);
            }
        }
        if (kt + 1 < T) {
            const int nb = (kt + 1) & 1;
            int kb = kq * 4;
            As[nb][kb + 0][rowA] = ar0.x; As[nb][kb + 1][rowA] = ar0.y;
            As[nb][kb + 2][rowA] = ar0.z; As[nb][kb + 3][rowA] = ar0.w;
            As[nb][kb + 0][rowA + 64] = ar1.x; As[nb][kb + 1][rowA + 64] = ar1.y;
            As[nb][kb + 2][rowA + 64] = ar1.z; As[nb][kb + 3][rowA + 64] = ar1.w;
            Bs[nb][kb + 0][rowA] = br0.x; Bs[nb][kb + 1][rowA] = br0.y;
            Bs[nb][kb + 2][rowA] = br0.z; Bs[nb][kb + 3][rowA] = br0.w;
            Bs[nb][kb + 0][rowA + 64] = br1.x; Bs[nb][kb + 1][rowA + 64] = br1.y;
            Bs[nb][kb + 2][rowA + 64] = br1.z; Bs[nb][kb + 3][rowA + 64] = br1.w;
            __syncthreads();
        }
    }

#pragma unroll
    for (int i = 0; i < 8; i++) {
        float o0, o1, o2, o3, o4, o5, o6, o7;
        up2(c2[i][0], o0, o1); up2(c2[i][1], o2, o3);
        up2(c2[i][2], o4, o5); up2(c2[i][3], o6, o7);
        float* Cp = C + (size_t)(m0 + ty * 8 + i) * HH + n0 + tx * 8;
        *(float4*)(Cp)     = make_float4(o0, o1, o2, o3);
        *(float4*)(Cp + 4) = make_float4(o4, o5, o6, o7);
    }
}

// ---------------- Ghost BN (VBS=128 -> one CTA per chunk) + GLU ----------------
__global__ void gbn_glu_kernel(const float* __restrict__ h, const float* __restrict__ gam,
                               const float* __restrict__ bet, float* __restrict__ outp) {
    __shared__ float sc[HH], sh[HH];
    int c = blockIdx.x, j = threadIdx.x;   // 384 threads
    const float* hc = h + (size_t)c * 128 * HH;
    float s = 0.f, q = 0.f;
#pragma unroll 4
    for (int r = 0; r < 128; r++) { float v = hc[(size_t)r * HH + j]; s += v; q += v * v; }
    float mean = s * (1.f / 128.f);
    float var  = q * (1.f / 128.f) - mean * mean;
    float inv  = 1.f / sqrtf(var + EPS_BN);
    float scale = gam[j] * inv;
    sc[j] = scale;
    sh[j] = bet[j] - mean * scale;
    __syncthreads();
    if (j < OUTF) {
        float sa = sc[j], ba = sh[j], sg = sc[j + OUTF], bg = sh[j + OUTF];
        float* op = outp + (size_t)c * 128 * OUTF + j;
        for (int r = 0; r < 128; r++) {
            float va = hc[(size_t)r * HH + j] * sa + ba;
            float vg = hc[(size_t)r * HH + j + OUTF] * sg + bg;
            op[(size_t)r * OUTF] = va * (1.f / (1.f + expf(-vg)));
        }
    }
}

// ---------------- epilogue: output sigmoid + att update ----------------
__global__ void epilogue_kernel(const float* __restrict__ dec, const float* __restrict__ enc,
                                float* __restrict__ outs, int do_att) {
    int blk = blockIdx.x, t = threadIdx.x;
    size_t base = (size_t)blk * 128;
    for (int idx = t; idx < 128 * NDOUT; idx += 256) {
        int r = idx >> 6, j = idx & 63;
        float v = dec[(base + r) * OUTF + j];
        outs[(base + r) * NDOUT + j] = 1.f / (1.f + expf(-v));
    }
    if (do_att) {
        for (int idx = t; idx < 128 * DD; idx += 256) {
            int r = idx >> 7, j = idx & 127;
            size_t i = base + r;
            float e = enc[i * OUTF + NDOUT + j];
            float m = g_M[i * DD + j];
            g_att[i * DD + j] = 1.3f * (1.f / (1.f + expf(-e))) * (1.f - m);
        }
    }
}

// ---------------- loss finalize (fixed-order reduction) ----------------
__global__ void loss_finalize_kernel(float* __restrict__ outp) {
    __shared__ float s[256];
    int t = threadIdx.x;
    float a = 0.f;
    for (int i = t; i < NSTEP * NCHUNK; i += 256) a += g_losspart[i];
    s[t] = a;
    __syncthreads();
    for (int o = 128; o; o >>= 1) {
        if (t < o) s[t] += s[t + o];
        __syncthreads();
    }
    if (t == 0) outp[0] = s[0] / ((float)BB * (float)NSTEP);
}

// ---------------- launch ----------------
extern "C" void kernel_launch(void* const* d_in, const int* in_sizes, int n_in,
                              void* d_out, int out_size) {
    (void)in_sizes; (void)n_in;
    const float* x   = (const float*)d_in[0];
    const float* ig  = (const float*)d_in[1];
    const float* ib  = (const float*)d_in[2];
    const float* eW0 = (const float*)d_in[3];
    const float* eg0 = (const float*)d_in[4];
    const float* eb0 = (const float*)d_in[5];
    const float* eW1 = (const float*)d_in[6];
    const float* eg1 = (const float*)d_in[7];
    const float* eb1 = (const float*)d_in[8];
    const float* dW0 = (const float*)d_in[9];
    const float* dg0 = (const float*)d_in[10];
    const float* db0 = (const float*)d_in[11];
    const float* dW1 = (const float*)d_in[12];
    const float* dg1 = (const float*)d_in[13];
    const float* db1 = (const float*)d_in[14];
    float* out = (float*)d_out;

    float *p_att, *p_a, *p_h, *p_enc;
    cudaGetSymbolAddress((void**)&p_att, g_att);
    cudaGetSymbolAddress((void**)&p_a, g_a);
    cudaGetSymbolAddress((void**)&p_h, g_h);
    cudaGetSymbolAddress((void**)&p_enc, g_enc);

    bn_partial_kernel<<<NCHUNK, 256>>>(x);
    bn_finalize_kernel<<<1, DD>>>(ig, ib);
    bn_apply_kernel<<<BB * DD / 4 / 256, 256>>>(x);

    dim3 gg(3, BB / 128);
    for (int s = 0; s < NSTEP; s++) {
        sparsemax_kernel<<<NCHUNK, 256>>>(s);
        if (s < NSTEP - 1) {   // enc path is dead at the last step
            gemm_nt_kernel<128><<<gg, 256>>>(p_att, eW0 + (size_t)s * HH * DD, p_h);
            gbn_glu_kernel<<<NCHUNK, HH>>>(p_h, eg0 + s * HH, eb0 + s * HH, p_a);
            gemm_nt_kernel<192><<<gg, 256>>>(p_a, eW1 + (size_t)s * HH * OUTF, p_h);
            gbn_glu_kernel<<<NCHUNK, HH>>>(p_h, eg1 + s * HH, eb1 + s * HH, p_enc);
        }
        gemm_nt_kernel<128><<<gg, 256>>>(p_att, dW0 + (size_t)s * HH * DD, p_h);
        gbn_glu_kernel<<<NCHUNK, HH>>>(p_h, dg0 + s * HH, db0 + s * HH, p_a);
        gemm_nt_kernel<192><<<gg, 256>>>(p_a, dW1 + (size_t)s * HH * OUTF, p_h);
        gbn_glu_kernel<<<NCHUNK, HH>>>(p_h, dg1 + s * HH, db1 + s * HH, p_a);
        epilogue_kernel<<<NCHUNK, 256>>>(p_a, p_enc, out + (size_t)s * BB * NDOUT,
                                         (s < NSTEP - 1) ? 1 : 0);
    }
    if (out_size > BB * NDOUT * NSTEP) {
        loss_finalize_kernel<<<1, 256>>>(out + (size_t)BB * NDOUT * NSTEP);
    }
}

// round 2
// speedup vs baseline: 1.3434x; 1.3434x over previous
#include <cuda_runtime.h>
#include <cuda_bf16.h>

// ---------------- problem constants ----------------
constexpr int BB     = 32768;   // batch
constexpr int DD     = 128;     // input dim
constexpr int OUTF   = 192;     // n_d + n_a
constexpr int HH     = 384;     // 2*OUTF
constexpr int NSTEP  = 3;
constexpr int NCHUNK = 256;     // BB / VBS(128)
constexpr int NDOUT  = 64;      // n_d
#define EPS_BN 1e-5f

// ---------------- scratch (device globals: allocation-free) ----------------
__device__ float g_xbn[BB * DD];            // BN'd input
__device__ float g_att[BB * DD];            // attention values (input to sparsemax)
__device__ float g_M[BB * DD];              // sparsemax mask
__device__ float g_h[BB * HH];              // GEMM output buffer (fp32)
__device__ float g_a[BB * OUTF];            // final GLU output (dec result, fp32)
__device__ float g_enc[BB * OUTF];          // enc result (fp32)
__device__ float g_bnpart[NCHUNK * 2 * DD];
__device__ float g_bnscale[DD];
__device__ float g_bnshift[DD];
__device__ float g_losspart[NSTEP * NCHUNK];

// split-bf16 activation buffers: A' = [hi | hi | lo] along K
__device__ __nv_bfloat16 g_ax[BB * 3 * DD];    // masked_x split  [BB, 384]
__device__ __nv_bfloat16 g_as[BB * 3 * OUTF];  // GLU0 out split  [BB, 576]

// split-bf16 weight buffers: W' = [hi | lo | hi] along K
__device__ __nv_bfloat16 g_eW0s[NSTEP * HH * 3 * DD];
__device__ __nv_bfloat16 g_eW1s[NSTEP * HH * 3 * OUTF];
__device__ __nv_bfloat16 g_dW0s[NSTEP * HH * 3 * DD];
__device__ __nv_bfloat16 g_dW1s[NSTEP * HH * 3 * OUTF];

// ---------------- mma / ldmatrix primitives ----------------
__device__ __forceinline__ void ldsm4(unsigned* r, const void* p) {
    unsigned a = (unsigned)__cvta_generic_to_shared(p);
    asm volatile("ldmatrix.sync.aligned.m8n8.x4.shared.b16 {%0,%1,%2,%3}, [%4];"
                 : "=r"(r[0]), "=r"(r[1]), "=r"(r[2]), "=r"(r[3]) : "r"(a));
}
__device__ __forceinline__ void mma16816(float* d, const unsigned* a, unsigned b0, unsigned b1) {
    asm volatile(
        "mma.sync.aligned.m16n8k16.row.col.f32.bf16.bf16.f32 "
        "{%0,%1,%2,%3}, {%4,%5,%6,%7}, {%8,%9}, {%0,%1,%2,%3};"
        : "+f"(d[0]), "+f"(d[1]), "+f"(d[2]), "+f"(d[3])
        : "r"(a[0]), "r"(a[1]), "r"(a[2]), "r"(a[3]), "r"(b0), "r"(b1));
}

// ---------------- BN stats (two-pass, deterministic) ----------------
__global__ void bn_partial_kernel(const float* __restrict__ x) {
    __shared__ float ss[256], sq[256];
    int t = threadIdx.x, blk = blockIdx.x;
    int col = t & 127, half = t >> 7;
    const float* xp = x + ((size_t)blk * 128 + half * 64) * DD + col;
    float s = 0.f, q = 0.f;
#pragma unroll 8
    for (int r = 0; r < 64; r++) { float v = xp[(size_t)r * DD]; s += v; q += v * v; }
    ss[t] = s; sq[t] = q;
    __syncthreads();
    if (t < 128) {
        g_bnpart[(blk * 2 + 0) * DD + t] = ss[t] + ss[t + 128];
        g_bnpart[(blk * 2 + 1) * DD + t] = sq[t] + sq[t + 128];
    }
}

__global__ void bn_finalize_kernel(const float* __restrict__ gam, const float* __restrict__ bet) {
    int c = threadIdx.x;   // 128 threads
    float s = 0.f, q = 0.f;
    for (int b = 0; b < NCHUNK; b++) {
        s += g_bnpart[(b * 2 + 0) * DD + c];
        q += g_bnpart[(b * 2 + 1) * DD + c];
    }
    float mean = s / (float)BB;
    float var  = q / (float)BB - mean * mean;
    float inv  = 1.f / sqrtf(var + EPS_BN);
    float sc   = gam[c] * inv;
    g_bnscale[c] = sc;
    g_bnshift[c] = bet[c] - mean * sc;
}

__global__ void bn_apply_kernel(const float* __restrict__ x) {
    int i = blockIdx.x * blockDim.x + threadIdx.x;   // over BB*DD/4 float4s
    if (i >= BB * DD / 4) return;
    float4 v = ((const float4*)x)[i];
    int c = (i & 31) * 4;   // DD/4 = 32 float4s per row
    v.x = v.x * g_bnscale[c + 0] + g_bnshift[c + 0];
    v.y = v.y * g_bnscale[c + 1] + g_bnshift[c + 1];
    v.z = v.z * g_bnscale[c + 2] + g_bnshift[c + 2];
    v.w = v.w * g_bnscale[c + 3] + g_bnshift[c + 3];
    ((float4*)g_xbn)[i] = v;
    ((float4*)g_att)[i] = make_float4(1.f, 1.f, 1.f, 1.f);
}

// ---------------- weight splitting: src [N=384, K] fp32 -> dst [384, 3K] bf16 ----
__global__ void wsplit_kernel(const float* __restrict__ src, __nv_bfloat16* __restrict__ dst, int K) {
    int i = blockIdx.x * 256 + threadIdx.x;
    if (i >= HH * K) return;
    int n = i / K, k = i - n * K;
    float w = src[i];
    __nv_bfloat16 h = __float2bfloat16(w);
    __nv_bfloat16 l = __float2bfloat16(w - __bfloat162float(h));
    __nv_bfloat16* row = dst + (size_t)n * 3 * K;
    row[k] = h; row[K + k] = l; row[2 * K + k] = h;   // [hi | lo | hi]
}

// ---------------- sparsemax + mask + loss + split-bf16 write ----------------
__global__ void sparsemax_kernel(int step) {
    __shared__ float wl[8];
    int t = threadIdx.x, lane = t & 31, w = t >> 5, blk = blockIdx.x;
    float acc = 0.f;
    for (int rr = 0; rr < 16; rr++) {
        size_t row = (size_t)blk * 128 + w * 16 + rr;
        const float* ap = g_att + row * DD;
        float z0 = ap[lane], z1 = ap[lane + 32], z2 = ap[lane + 64], z3 = ap[lane + 96];
        float mx = fmaxf(fmaxf(z0, z1), fmaxf(z2, z3));
#pragma unroll
        for (int o = 16; o; o >>= 1) mx = fmaxf(mx, __shfl_xor_sync(0xffffffffu, mx, o));
        z0 -= mx; z1 -= mx; z2 -= mx; z3 -= mx;
        float sm = z0 + z1 + z2 + z3;
#pragma unroll
        for (int o = 16; o; o >>= 1) sm += __shfl_xor_sync(0xffffffffu, sm, o);
        float tau = (sm - 1.f) * (1.f / 128.f);
        int cnt = 128;
        for (int it = 0; it < 64; it++) {
            float s = 0.f; int c = 0;
            if (z0 > tau) { s += z0; c++; }
            if (z1 > tau) { s += z1; c++; }
            if (z2 > tau) { s += z2; c++; }
            if (z3 > tau) { s += z3; c++; }
#pragma unroll
            for (int o = 16; o; o >>= 1) {
                s += __shfl_xor_sync(0xffffffffu, s, o);
                c += __shfl_xor_sync(0xffffffffu, c, o);
            }
            if (c == cnt) break;
            cnt = c; tau = (s - 1.f) / (float)c;
        }
        const float* xp = g_xbn + row * DD;
        float* Mp = g_M + row * DD;
        __nv_bfloat16* axp = g_ax + row * (3 * DD);
        float m[4] = {fmaxf(z0 - tau, 0.f), fmaxf(z1 - tau, 0.f),
                      fmaxf(z2 - tau, 0.f), fmaxf(z3 - tau, 0.f)};
        float rl = 0.f;
#pragma unroll
        for (int i = 0; i < 4; i++) {
            int c = lane + 32 * i;
            Mp[c] = m[i];
            float mv = m[i] * xp[c];
            __nv_bfloat16 h = __float2bfloat16(mv);
            __nv_bfloat16 l = __float2bfloat16(mv - __bfloat162float(h));
            axp[c] = h; axp[DD + c] = h; axp[2 * DD + c] = l;   // [hi | hi | lo]
            rl += m[i] * logf(m[i] + 1e-10f);
        }
#pragma unroll
        for (int o = 16; o; o >>= 1) rl += __shfl_xor_sync(0xffffffffu, rl, o);
        acc += rl;
    }
    if (lane == 0) wl[w] = acc;
    __syncthreads();
    if (t == 0) {
        float s = 0.f;
        for (int i = 0; i < 8; i++) s += wl[i];
        g_losspart[step * NCHUNK + blk] = s;
    }
}

// ---------------- bf16 tensor-core GEMM: C[M,384] = A'[M,K3] * W'[384,K3]^T ----
// TN layout: A row-major K-major, W row-major K-major (= B col-major). K3 in {384, 576}.
template <int K3>
__global__ __launch_bounds__(256) void gemm_bf16_kernel(
        const __nv_bfloat16* __restrict__ A,
        const __nv_bfloat16* __restrict__ W,
        float* __restrict__ C) {
    constexpr int T = K3 / 32;                 // k-tiles of 32
    __shared__ __align__(16) __nv_bfloat16 As[2][128][40];   // padded: stride 5x16B, coprime 8
    __shared__ __align__(16) __nv_bfloat16 Bs[2][128][40];

    const int t = threadIdx.x;
    const int m0 = blockIdx.y * 128, n0 = blockIdx.x * 128;
    const int lrow = t >> 1;              // 0..127
    const int lcol = (t & 1) * 16;        // 0 or 16

    const __nv_bfloat16* Ag = A + (size_t)(m0 + lrow) * K3 + lcol;
    const __nv_bfloat16* Wg = W + (size_t)(n0 + lrow) * K3 + lcol;

    const int warp = t >> 5, lane = t & 31;
    const int wm = warp >> 1;             // 0..3  (32 rows each)
    const int wn = warp & 1;              // 0..1  (64 cols each)
    const int lr = lane & 15, lc = (lane >> 4) * 8;

    float d[2][8][4];
#pragma unroll
    for (int i = 0; i < 2; i++)
#pragma unroll
        for (int j = 0; j < 8; j++)
#pragma unroll
            for (int k = 0; k < 4; k++) d[i][j][k] = 0.f;

    uint4 ra0, ra1, rb0, rb1;
    ra0 = *(const uint4*)(Ag);     ra1 = *(const uint4*)(Ag + 8);
    rb0 = *(const uint4*)(Wg);     rb1 = *(const uint4*)(Wg + 8);
    *(uint4*)&As[0][lrow][lcol] = ra0;  *(uint4*)&As[0][lrow][lcol + 8] = ra1;
    *(uint4*)&Bs[0][lrow][lcol] = rb0;  *(uint4*)&Bs[0][lrow][lcol + 8] = rb1;
    __syncthreads();

    for (int kt = 0; kt < T; kt++) {
        const int buf = kt & 1;
        if (kt + 1 < T) {
            const __nv_bfloat16* Ag2 = Ag + (kt + 1) * 32;
            const __nv_bfloat16* Wg2 = Wg + (kt + 1) * 32;
            ra0 = *(const uint4*)(Ag2);  ra1 = *(const uint4*)(Ag2 + 8);
            rb0 = *(const uint4*)(Wg2);  rb1 = *(const uint4*)(Wg2 + 8);
        }
#pragma unroll
        for (int ks = 0; ks < 2; ks++) {
            unsigned afr[2][4], bfr[4][4];
            const int krow = ks * 16 + lc;
#pragma unroll
            for (int mf = 0; mf < 2; mf++)
                ldsm4(afr[mf], &As[buf][wm * 32 + mf * 16 + lr][krow]);
#pragma unroll
            for (int nb = 0; nb < 4; nb++)
                ldsm4(bfr[nb], &Bs[buf][wn * 64 + nb * 16 + lr][krow]);
#pragma unroll
            for (int mf = 0; mf < 2; mf++)
#pragma unroll
                for (int n8 = 0; n8 < 8; n8++) {
                    const int nb = n8 >> 1, hf = n8 & 1;
                    mma16816(d[mf][n8], afr[mf], bfr[nb][hf], bfr[nb][hf + 2]);
                }
        }
        if (kt + 1 < T) {
            const int nb = (kt + 1) & 1;
            *(uint4*)&As[nb][lrow][lcol] = ra0;  *(uint4*)&As[nb][lrow][lcol + 8] = ra1;
            *(uint4*)&Bs[nb][lrow][lcol] = rb0;  *(uint4*)&Bs[nb][lrow][lcol + 8] = rb1;
            __syncthreads();
        }
    }

#pragma unroll
    for (int mf = 0; mf < 2; mf++)
#pragma unroll
        for (int n8 = 0; n8 < 8; n8++) {
            int row = m0 + wm * 32 + mf * 16 + (lane >> 2);
            int col = n0 + wn * 64 + n8 * 8 + (lane & 3) * 2;
            *(float2*)&C[(size_t)row * HH + col]       = make_float2(d[mf][n8][0], d[mf][n8][1]);
            *(float2*)&C[(size_t)(row + 8) * HH + col] = make_float2(d[mf][n8][2], d[mf][n8][3]);
        }
}

// ---------------- Ghost BN (VBS=128 -> one CTA per chunk) + GLU ----------------
// SPLIT=true: write split-bf16 [BB, 576] for next GEMM; else fp32 [BB, 192].
template <bool SPLIT>
__global__ void gbn_glu_kernel(const float* __restrict__ h, const float* __restrict__ gam,
                               const float* __restrict__ bet,
                               float* __restrict__ outp, __nv_bfloat16* __restrict__ outs) {
    __shared__ float sc[HH], sh[HH];
    int c = blockIdx.x, j = threadIdx.x;   // 384 threads
    const float* hc = h + (size_t)c * 128 * HH;
    float s = 0.f, q = 0.f;
#pragma unroll 4
    for (int r = 0; r < 128; r++) { float v = hc[(size_t)r * HH + j]; s += v; q += v * v; }
    float mean = s * (1.f / 128.f);
    float var  = q * (1.f / 128.f) - mean * mean;
    float inv  = 1.f / sqrtf(var + EPS_BN);
    float scale = gam[j] * inv;
    sc[j] = scale;
    sh[j] = bet[j] - mean * scale;
    __syncthreads();
    if (j < OUTF) {
        float sa = sc[j], ba = sh[j], sg = sc[j + OUTF], bg = sh[j + OUTF];
        for (int r = 0; r < 128; r++) {
            float va = hc[(size_t)r * HH + j] * sa + ba;
            float vg = hc[(size_t)r * HH + j + OUTF] * sg + bg;
            float v = va * (1.f / (1.f + expf(-vg)));
            if (SPLIT) {
                __nv_bfloat16 hi = __float2bfloat16(v);
                __nv_bfloat16 lo = __float2bfloat16(v - __bfloat162float(hi));
                __nv_bfloat16* sp = outs + ((size_t)c * 128 + r) * (3 * OUTF) + j;
                sp[0] = hi; sp[OUTF] = hi; sp[2 * OUTF] = lo;   // [hi | hi | lo]
            } else {
                outp[((size_t)c * 128 + r) * OUTF + j] = v;
            }
        }
    }
}

// ---------------- epilogue: output sigmoid + att update ----------------
__global__ void epilogue_kernel(const float* __restrict__ dec, const float* __restrict__ enc,
                                float* __restrict__ outs, int do_att) {
    int blk = blockIdx.x, t = threadIdx.x;
    size_t base = (size_t)blk * 128;
    for (int idx = t; idx < 128 * NDOUT; idx += 256) {
        int r = idx >> 6, j = idx & 63;
        float v = dec[(base + r) * OUTF + j];
        outs[(base + r) * NDOUT + j] = 1.f / (1.f + expf(-v));
    }
    if (do_att) {
        for (int idx = t; idx < 128 * DD; idx += 256) {
            int r = idx >> 7, j = idx & 127;
            size_t i = base + r;
            float e = enc[i * OUTF + NDOUT + j];
            float m = g_M[i * DD + j];
            g_att[i * DD + j] = 1.3f * (1.f / (1.f + expf(-e))) * (1.f - m);
        }
    }
}

// ---------------- loss finalize (fixed-order reduction) ----------------
__global__ void loss_finalize_kernel(float* __restrict__ outp) {
    __shared__ float s[256];
    int t = threadIdx.x;
    float a = 0.f;
    for (int i = t; i < NSTEP * NCHUNK; i += 256) a += g_losspart[i];
    s[t] = a;
    __syncthreads();
    for (int o = 128; o; o >>= 1) {
        if (t < o) s[t] += s[t + o];
        __syncthreads();
    }
    if (t == 0) outp[0] = s[0] / ((float)BB * (float)NSTEP);
}

// ---------------- launch ----------------
extern "C" void kernel_launch(void* const* d_in, const int* in_sizes, int n_in,
                              void* d_out, int out_size) {
    (void)in_sizes; (void)n_in;
    const float* x   = (const float*)d_in[0];
    const float* ig  = (const float*)d_in[1];
    const float* ib  = (const float*)d_in[2];
    const float* eW0 = (const float*)d_in[3];
    const float* eg0 = (const float*)d_in[4];
    const float* eb0 = (const float*)d_in[5];
    const float* eW1 = (const float*)d_in[6];
    const float* eg1 = (const float*)d_in[7];
    const float* eb1 = (const float*)d_in[8];
    const float* dW0 = (const float*)d_in[9];
    const float* dg0 = (const float*)d_in[10];
    const float* db0 = (const float*)d_in[11];
    const float* dW1 = (const float*)d_in[12];
    const float* dg1 = (const float*)d_in[13];
    const float* db1 = (const float*)d_in[14];
    float* out = (float*)d_out;

    float *p_h, *p_a, *p_enc;
    __nv_bfloat16 *p_ax, *p_as, *p_eW0s, *p_eW1s, *p_dW0s, *p_dW1s;
    cudaGetSymbolAddress((void**)&p_h, g_h);
    cudaGetSymbolAddress((void**)&p_a, g_a);
    cudaGetSymbolAddress((void**)&p_enc, g_enc);
    cudaGetSymbolAddress((void**)&p_ax, g_ax);
    cudaGetSymbolAddress((void**)&p_as, g_as);
    cudaGetSymbolAddress((void**)&p_eW0s, g_eW0s);
    cudaGetSymbolAddress((void**)&p_eW1s, g_eW1s);
    cudaGetSymbolAddress((void**)&p_dW0s, g_dW0s);
    cudaGetSymbolAddress((void**)&p_dW1s, g_dW1s);

    bn_partial_kernel<<<NCHUNK, 256>>>(x);
    bn_finalize_kernel<<<1, DD>>>(ig, ib);
    bn_apply_kernel<<<BB * DD / 4 / 256, 256>>>(x);

    // split weights (tiny)
    const int g128 = (HH * DD + 255) / 256, g192 = (HH * OUTF + 255) / 256;
    for (int s = 0; s < NSTEP; s++) {
        if (s < NSTEP - 1) {   // enc weights dead at last step
            wsplit_kernel<<<g128, 256>>>(eW0 + (size_t)s * HH * DD,  p_eW0s + (size_t)s * HH * 3 * DD,  DD);
            wsplit_kernel<<<g192, 256>>>(eW1 + (size_t)s * HH * OUTF, p_eW1s + (size_t)s * HH * 3 * OUTF, OUTF);
        }
        wsplit_kernel<<<g128, 256>>>(dW0 + (size_t)s * HH * DD,  p_dW0s + (size_t)s * HH * 3 * DD,  DD);
        wsplit_kernel<<<g192, 256>>>(dW1 + (size_t)s * HH * OUTF, p_dW1s + (size_t)s * HH * 3 * OUTF, OUTF);
    }

    dim3 gg(3, BB / 128);
    for (int s = 0; s < NSTEP; s++) {
        sparsemax_kernel<<<NCHUNK, 256>>>(s);
        if (s < NSTEP - 1) {   // enc path is dead at the last step
            gemm_bf16_kernel<3 * DD><<<gg, 256>>>(p_ax, p_eW0s + (size_t)s * HH * 3 * DD, p_h);
            gbn_glu_kernel<true><<<NCHUNK, HH>>>(p_h, eg0 + s * HH, eb0 + s * HH, nullptr, p_as);
            gemm_bf16_kernel<3 * OUTF><<<gg, 256>>>(p_as, p_eW1s + (size_t)s * HH * 3 * OUTF, p_h);
            gbn_glu_kernel<false><<<NCHUNK, HH>>>(p_h, eg1 + s * HH, eb1 + s * HH, p_enc, nullptr);
        }
        gemm_bf16_kernel<3 * DD><<<gg, 256>>>(p_ax, p_dW0s + (size_t)s * HH * 3 * DD, p_h);
        gbn_glu_kernel<true><<<NCHUNK, HH>>>(p_h, dg0 + s * HH, db0 + s * HH, nullptr, p_as);
        gemm_bf16_kernel<3 * OUTF><<<gg, 256>>>(p_as, p_dW1s + (size_t)s * HH * 3 * OUTF, p_h);
        gbn_glu_kernel<false><<<NCHUNK, HH>>>(p_h, dg1 + s * HH, db1 + s * HH, p_a, nullptr);
        epilogue_kernel<<<NCHUNK, 256>>>(p_a, p_enc, out + (size_t)s * BB * NDOUT,
                                         (s < NSTEP - 1) ? 1 : 0);
    }
    if (out_size > BB * NDOUT * NSTEP) {
        loss_finalize_kernel<<<1, 256>>>(out + (size_t)BB * NDOUT * NSTEP);
    }
}

// round 6
// speedup vs baseline: 2.5062x; 1.8655x over previous
#include <cuda_runtime.h>
#include <cuda_bf16.h>
#include <cstdint>

// ---------------- problem constants ----------------
constexpr int BB     = 32768;   // batch
constexpr int DD     = 128;     // input dim
constexpr int OUTF   = 192;     // n_d + n_a
constexpr int HH     = 384;     // 2*OUTF
constexpr int NSTEP  = 3;
constexpr int NDOUT  = 64;      // n_d
constexpr int SMBLK  = 1024;    // sparsemax blocks (32 rows each)
#define EPS_BN 1e-5f

// ---------------- scratch (device globals: allocation-free) ----------------
__device__ float g_xbn[BB * DD];
__device__ float g_att[BB * DD];
__device__ float g_M[BB * DD];
__device__ float g_a[BB * OUTF];            // dec result (only cols 0..63 valid/used)
__device__ float g_enc[BB * OUTF];          // enc result (only cols 64..191 valid/used)
__device__ float g_bnpart[256 * 2 * DD];
__device__ float g_bnscale[DD];
__device__ float g_bnshift[DD];
__device__ float g_losspart[NSTEP * SMBLK];

// split-bf16 activation buffers: A' = [hi | hi | lo] along K
__device__ __align__(128) __nv_bfloat16 g_ax[BB * 3 * DD];     // masked_x  [BB, 384]
__device__ __align__(128) __nv_bfloat16 g_as[BB * 3 * OUTF];   // GLU0 out  [BB, 576]

// split-bf16 PERMUTED weights: W' = [hi | lo | hi] along K; row perm: n<192->2n else 2(n-192)+1
__device__ __align__(128) __nv_bfloat16 g_eW0s[NSTEP * HH * 3 * DD];
__device__ __align__(128) __nv_bfloat16 g_eW1s[NSTEP * HH * 3 * OUTF];
__device__ __align__(128) __nv_bfloat16 g_dW0s[NSTEP * HH * 3 * DD];
__device__ __align__(128) __nv_bfloat16 g_dW1s[NSTEP * HH * 3 * OUTF];

// ---------------- mma / ldmatrix primitives ----------------
__device__ __forceinline__ void ldsm4(unsigned* r, const void* p) {
    unsigned a = (unsigned)__cvta_generic_to_shared(p);
    asm volatile("ldmatrix.sync.aligned.m8n8.x4.shared.b16 {%0,%1,%2,%3}, [%4];"
                 : "=r"(r[0]), "=r"(r[1]), "=r"(r[2]), "=r"(r[3]) : "r"(a));
}
__device__ __forceinline__ void mma16816(float* d, const unsigned* a, unsigned b0, unsigned b1) {
    asm volatile(
        "mma.sync.aligned.m16n8k16.row.col.f32.bf16.bf16.f32 "
        "{%0,%1,%2,%3}, {%4,%5,%6,%7}, {%8,%9}, {%0,%1,%2,%3};"
        : "+f"(d[0]), "+f"(d[1]), "+f"(d[2]), "+f"(d[3])
        : "r"(a[0]), "r"(a[1]), "r"(a[2]), "r"(a[3]), "r"(b0), "r"(b1));
}

// ---------------- smem plan for fused kernel (dynamic, temporally reused) ----
// mainloop: As[2][128][40] bf16 (20480B) + Bs[2][128][40] (20480B) = 40960B
// epilogue: stage 128 x 132 fp32 = 67584B (reuses the same region)
// tail:     sc/sh 512B each after stage
constexpr int STAGE_LD   = 132;
constexpr int SM_SC_OFF  = 128 * STAGE_LD * 4;          // 67584
constexpr int SM_SH_OFF  = SM_SC_OFF + 512;
constexpr int SMEM_BYTES = SM_SH_OFF + 512;             // 68608

// ---------------- BN stats ----------------
__global__ void bn_partial_kernel(const float* __restrict__ x) {
    __shared__ float ss[256], sq[256];
    int t = threadIdx.x, blk = blockIdx.x;
    int col = t & 127, half = t >> 7;
    const float* xp = x + ((size_t)blk * 128 + half * 64) * DD + col;
    float s = 0.f, q = 0.f;
#pragma unroll 8
    for (int r = 0; r < 64; r++) { float v = xp[(size_t)r * DD]; s += v; q += v * v; }
    ss[t] = s; sq[t] = q;
    __syncthreads();
    if (t < 128) {
        g_bnpart[(blk * 2 + 0) * DD + t] = ss[t] + ss[t + 128];
        g_bnpart[(blk * 2 + 1) * DD + t] = sq[t] + sq[t + 128];
    }
}

__global__ void bn_finalize_kernel(const float* __restrict__ gam, const float* __restrict__ bet) {
    int c = threadIdx.x;
    float s = 0.f, q = 0.f;
    for (int b = 0; b < 256; b++) {
        s += g_bnpart[(b * 2 + 0) * DD + c];
        q += g_bnpart[(b * 2 + 1) * DD + c];
    }
    float mean = s / (float)BB;
    float var  = q / (float)BB - mean * mean;
    float inv  = 1.f / sqrtf(var + EPS_BN);
    float sc   = gam[c] * inv;
    g_bnscale[c] = sc;
    g_bnshift[c] = bet[c] - mean * sc;
}

__global__ void bn_apply_kernel(const float* __restrict__ x) {
    int i = blockIdx.x * blockDim.x + threadIdx.x;
    if (i >= BB * DD / 4) return;
    float4 v = ((const float4*)x)[i];
    int c = (i & 31) * 4;
    v.x = v.x * g_bnscale[c + 0] + g_bnshift[c + 0];
    v.y = v.y * g_bnscale[c + 1] + g_bnshift[c + 1];
    v.z = v.z * g_bnscale[c + 2] + g_bnshift[c + 2];
    v.w = v.w * g_bnscale[c + 3] + g_bnshift[c + 3];
    ((float4*)g_xbn)[i] = v;
    ((float4*)g_att)[i] = make_float4(1.f, 1.f, 1.f, 1.f);
}

// ---------------- weight split + GLU-pair permutation ----------------
// src [384, K] fp32 -> dst [384 permuted, 3K] bf16  rows: n<192 -> 2n ; n>=192 -> 2(n-192)+1
__global__ void wsplit_kernel(const float* __restrict__ src, __nv_bfloat16* __restrict__ dst, int K) {
    int i = blockIdx.x * 256 + threadIdx.x;
    if (i >= HH * K) return;
    int n = i / K, k = i - n * K;
    int perm = (n < OUTF) ? (2 * n) : (2 * (n - OUTF) + 1);
    float w = src[i];
    __nv_bfloat16 h = __float2bfloat16(w);
    __nv_bfloat16 l = __float2bfloat16(w - __bfloat162float(h));
    __nv_bfloat16* row = dst + (size_t)perm * 3 * K;
    row[k] = h; row[K + k] = l; row[2 * K + k] = h;   // [hi | lo | hi]
}

// ---------------- sparsemax + mask + loss + split-bf16 write ----------------
__global__ void sparsemax_kernel(int step) {
    __shared__ float wl[8];
    int t = threadIdx.x, lane = t & 31, w = t >> 5, blk = blockIdx.x;
    float acc = 0.f;
    for (int rr = 0; rr < 4; rr++) {
        size_t row = (size_t)blk * 32 + w * 4 + rr;
        const float* ap = g_att + row * DD;
        float z0 = ap[lane], z1 = ap[lane + 32], z2 = ap[lane + 64], z3 = ap[lane + 96];
        float mx = fmaxf(fmaxf(z0, z1), fmaxf(z2, z3));
#pragma unroll
        for (int o = 16; o; o >>= 1) mx = fmaxf(mx, __shfl_xor_sync(0xffffffffu, mx, o));
        z0 -= mx; z1 -= mx; z2 -= mx; z3 -= mx;
        float sm = z0 + z1 + z2 + z3;
#pragma unroll
        for (int o = 16; o; o >>= 1) sm += __shfl_xor_sync(0xffffffffu, sm, o);
        float tau = (sm - 1.f) * (1.f / 128.f);
        int cnt = 128;
        for (int it = 0; it < 64; it++) {
            float s = 0.f; int c = 0;
            if (z0 > tau) { s += z0; c++; }
            if (z1 > tau) { s += z1; c++; }
            if (z2 > tau) { s += z2; c++; }
            if (z3 > tau) { s += z3; c++; }
#pragma unroll
            for (int o = 16; o; o >>= 1) {
                s += __shfl_xor_sync(0xffffffffu, s, o);
                c += __shfl_xor_sync(0xffffffffu, c, o);
            }
            if (c == cnt) break;
            cnt = c; tau = (s - 1.f) / (float)c;
        }
        const float* xp = g_xbn + row * DD;
        float* Mp = g_M + row * DD;
        __nv_bfloat16* axp = g_ax + row * (3 * DD);
        float m[4] = {fmaxf(z0 - tau, 0.f), fmaxf(z1 - tau, 0.f),
                      fmaxf(z2 - tau, 0.f), fmaxf(z3 - tau, 0.f)};
        float rl = 0.f;
#pragma unroll
        for (int i = 0; i < 4; i++) {
            int c = lane + 32 * i;
            Mp[c] = m[i];
            float mv = m[i] * xp[c];
            __nv_bfloat16 h = __float2bfloat16(mv);
            __nv_bfloat16 l = __float2bfloat16(mv - __bfloat162float(h));
            axp[c] = h; axp[DD + c] = h; axp[2 * DD + c] = l;   // [hi | hi | lo]
            rl += m[i] * logf(m[i] + 1e-10f);
        }
#pragma unroll
        for (int o = 16; o; o >>= 1) rl += __shfl_xor_sync(0xffffffffu, rl, o);
        acc += rl;
    }
    if (lane == 0) wl[w] = acc;
    __syncthreads();
    if (t == 0) {
        float s = 0.f;
        for (int i = 0; i < 8; i++) s += wl[i];
        g_losspart[step * SMBLK + blk] = s;
    }
}

// ---------------- fused bf16 mma.sync GEMM + GhostBN + GLU ----------------
// Tile: 128 rows (= one GBN chunk) x 128 permuted cols. nx = blockIdx.x + nxoff.
// After GEMM: per-col BN over this CTA's 128 rows, GLU on adjacent col pairs.
// SPLIT: write split-bf16 [BB, 3*OUTF]; else fp32 [BB, OUTF].
template <int K3, bool SPLIT>
__global__ __launch_bounds__(256, 2) void gemm_glu_kernel(
        const __nv_bfloat16* __restrict__ A,
        const __nv_bfloat16* __restrict__ W,
        const float* __restrict__ gam, const float* __restrict__ bet,
        float* __restrict__ outp, __nv_bfloat16* __restrict__ outs,
        int nxoff) {
    extern __shared__ __align__(16) char smem[];
    __nv_bfloat16* Asm = (__nv_bfloat16*)smem;        // [2][128][40]
    __nv_bfloat16* Bsm = Asm + 2 * 128 * 40;          // [2][128][40]
    constexpr int T = K3 / 32;                        // k-tiles of 32

    const int t = threadIdx.x;
    const int m0 = blockIdx.y * 128;
    const int nx = blockIdx.x + nxoff;                // permuted 128-col block
    const int n0 = nx * 128;
    const int lrow = t >> 1;                          // 0..127
    const int lcol = (t & 1) * 16;                    // 0 or 16

    const __nv_bfloat16* Ag = A + (size_t)(m0 + lrow) * K3 + lcol;
    const __nv_bfloat16* Wg = W + (size_t)(n0 + lrow) * K3 + lcol;

    const int warp = t >> 5, lane = t & 31;
    const int wm = warp >> 1;                         // 0..3 (32 rows each)
    const int wn = warp & 1;                          // 0..1 (64 cols each)
    const int lr = lane & 15, lc = (lane >> 4) * 8;

    float d[2][8][4];
#pragma unroll
    for (int i = 0; i < 2; i++)
#pragma unroll
        for (int j = 0; j < 8; j++)
#pragma unroll
            for (int k = 0; k < 4; k++) d[i][j][k] = 0.f;

    uint4 ra0, ra1, rb0, rb1;
    ra0 = *(const uint4*)(Ag);     ra1 = *(const uint4*)(Ag + 8);
    rb0 = *(const uint4*)(Wg);     rb1 = *(const uint4*)(Wg + 8);
    *(uint4*)&Asm[lrow * 40 + lcol] = ra0;  *(uint4*)&Asm[lrow * 40 + lcol + 8] = ra1;
    *(uint4*)&Bsm[lrow * 40 + lcol] = rb0;  *(uint4*)&Bsm[lrow * 40 + lcol + 8] = rb1;
    __syncthreads();

    for (int kt = 0; kt < T; kt++) {
        const int bo = (kt & 1) * 128 * 40;           // buffer element offset
        if (kt + 1 < T) {
            const __nv_bfloat16* Ag2 = Ag + (kt + 1) * 32;
            const __nv_bfloat16* Wg2 = Wg + (kt + 1) * 32;
            ra0 = *(const uint4*)(Ag2);  ra1 = *(const uint4*)(Ag2 + 8);
            rb0 = *(const uint4*)(Wg2);  rb1 = *(const uint4*)(Wg2 + 8);
        }
#pragma unroll
        for (int ks = 0; ks < 2; ks++) {
            unsigned afr[2][4], bfr[4][4];
            const int krow = ks * 16 + lc;
#pragma unroll
            for (int mf = 0; mf < 2; mf++)
                ldsm4(afr[mf], &Asm[bo + (wm * 32 + mf * 16 + lr) * 40 + krow]);
#pragma unroll
            for (int nb = 0; nb < 4; nb++)
                ldsm4(bfr[nb], &Bsm[bo + (wn * 64 + nb * 16 + lr) * 40 + krow]);
#pragma unroll
            for (int mf = 0; mf < 2; mf++)
#pragma unroll
                for (int n8 = 0; n8 < 8; n8++) {
                    const int nb = n8 >> 1, hf = n8 & 1;
                    mma16816(d[mf][n8], afr[mf], bfr[nb][hf], bfr[nb][hf + 2]);
                }
        }
        if (kt + 1 < T) {
            const int no = ((kt + 1) & 1) * 128 * 40;
            *(uint4*)&Asm[no + lrow * 40 + lcol] = ra0;  *(uint4*)&Asm[no + lrow * 40 + lcol + 8] = ra1;
            *(uint4*)&Bsm[no + lrow * 40 + lcol] = rb0;  *(uint4*)&Bsm[no + lrow * 40 + lcol + 8] = rb1;
            __syncthreads();
        }
    }
    __syncthreads();   // mainloop fully done; smem region is now free for the stage

    // --- write accumulators into fp32 stage [128][132] ---
    float* stage = (float*)smem;
#pragma unroll
    for (int mf = 0; mf < 2; mf++)
#pragma unroll
        for (int n8 = 0; n8 < 8; n8++) {
            int r_ = wm * 32 + mf * 16 + (lane >> 2);
            int c_ = wn * 64 + n8 * 8 + (lane & 3) * 2;
            stage[r_ * STAGE_LD + c_]           = d[mf][n8][0];
            stage[r_ * STAGE_LD + c_ + 1]       = d[mf][n8][1];
            stage[(r_ + 8) * STAGE_LD + c_]     = d[mf][n8][2];
            stage[(r_ + 8) * STAGE_LD + c_ + 1] = d[mf][n8][3];
        }
    __syncthreads();

    // --- GhostBN per column (this CTA's 128 rows == one GBN chunk) ---
    float* scp = (float*)(smem + SM_SC_OFF);
    float* shp = (float*)(smem + SM_SH_OFF);
    if (t < 128) {
        float s = 0.f, q = 0.f;
#pragma unroll 4
        for (int r = 0; r < 128; r++) {
            float v = stage[r * STAGE_LD + t];
            s += v; q += v * v;
        }
        float mean = s * (1.f / 128.f);
        float var  = q * (1.f / 128.f) - mean * mean;
        int ncol = n0 + t;                 // permuted col
        int u = ncol >> 1, p = ncol & 1;
        int orig = u + p * OUTF;
        float scale = gam[orig] / sqrtf(var + EPS_BN);
        scp[t] = scale;
        shp[t] = bet[orig] - mean * scale;
    }
    __syncthreads();

    // --- GLU on adjacent pairs + output write ---
    for (int idx = t; idx < 128 * 64; idx += 256) {
        int r = idx >> 6, up = idx & 63;
        float a = stage[r * STAGE_LD + 2 * up]     * scp[2 * up]     + shp[2 * up];
        float g = stage[r * STAGE_LD + 2 * up + 1] * scp[2 * up + 1] + shp[2 * up + 1];
        float v = a * (1.f / (1.f + expf(-g)));
        int u = nx * 64 + up;
        size_t row = (size_t)(m0 + r);
        if (SPLIT) {
            __nv_bfloat16 hi = __float2bfloat16(v);
            __nv_bfloat16 lo = __float2bfloat16(v - __bfloat162float(hi));
            __nv_bfloat16* sp = outs + row * (3 * OUTF);
            sp[u] = hi; sp[OUTF + u] = hi; sp[2 * OUTF + u] = lo;   // [hi | hi | lo]
        } else {
            outp[row * OUTF + u] = v;
        }
    }
}

// ---------------- epilogue: output sigmoid + att update ----------------
__global__ void epilogue_kernel(const float* __restrict__ dec, const float* __restrict__ enc,
                                float* __restrict__ outs, int do_att) {
    int blk = blockIdx.x, t = threadIdx.x;
    size_t base = (size_t)blk * 128;
    for (int idx = t; idx < 128 * NDOUT; idx += 256) {
        int r = idx >> 6, j = idx & 63;
        float v = dec[(base + r) * OUTF + j];
        outs[(base + r) * NDOUT + j] = 1.f / (1.f + expf(-v));
    }
    if (do_att) {
        for (int idx = t; idx < 128 * DD; idx += 256) {
            int r = idx >> 7, j = idx & 127;
            size_t i = base + r;
            float e = enc[i * OUTF + NDOUT + j];
            float m = g_M[i * DD + j];
            g_att[i * DD + j] = 1.3f * (1.f / (1.f + expf(-e))) * (1.f - m);
        }
    }
}

// ---------------- loss finalize ----------------
__global__ void loss_finalize_kernel(float* __restrict__ outp) {
    __shared__ float s[256];
    int t = threadIdx.x;
    float a = 0.f;
    for (int i = t; i < NSTEP * SMBLK; i += 256) a += g_losspart[i];
    s[t] = a;
    __syncthreads();
    for (int o = 128; o; o >>= 1) {
        if (t < o) s[t] += s[t + o];
        __syncthreads();
    }
    if (t == 0) outp[0] = s[0] / ((float)BB * (float)NSTEP);
}

// ---------------- launch ----------------
extern "C" void kernel_launch(void* const* d_in, const int* in_sizes, int n_in,
                              void* d_out, int out_size) {
    (void)in_sizes; (void)n_in;
    const float* x   = (const float*)d_in[0];
    const float* ig  = (const float*)d_in[1];
    const float* ib  = (const float*)d_in[2];
    const float* eW0 = (const float*)d_in[3];
    const float* eg0 = (const float*)d_in[4];
    const float* eb0 = (const float*)d_in[5];
    const float* eW1 = (const float*)d_in[6];
    const float* eg1 = (const float*)d_in[7];
    const float* eb1 = (const float*)d_in[8];
    const float* dW0 = (const float*)d_in[9];
    const float* dg0 = (const float*)d_in[10];
    const float* db0 = (const float*)d_in[11];
    const float* dW1 = (const float*)d_in[12];
    const float* dg1 = (const float*)d_in[13];
    const float* db1 = (const float*)d_in[14];
    float* out = (float*)d_out;

    float *p_a, *p_enc;
    __nv_bfloat16 *p_ax, *p_as, *p_eW0s, *p_eW1s, *p_dW0s, *p_dW1s;
    cudaGetSymbolAddress((void**)&p_a, g_a);
    cudaGetSymbolAddress((void**)&p_enc, g_enc);
    cudaGetSymbolAddress((void**)&p_ax, g_ax);
    cudaGetSymbolAddress((void**)&p_as, g_as);
    cudaGetSymbolAddress((void**)&p_eW0s, g_eW0s);
    cudaGetSymbolAddress((void**)&p_eW1s, g_eW1s);
    cudaGetSymbolAddress((void**)&p_dW0s, g_dW0s);
    cudaGetSymbolAddress((void**)&p_dW1s, g_dW1s);

    cudaFuncSetAttribute(gemm_glu_kernel<3 * DD, true>,
                         cudaFuncAttributeMaxDynamicSharedMemorySize, SMEM_BYTES);
    cudaFuncSetAttribute(gemm_glu_kernel<3 * OUTF, false>,
                         cudaFuncAttributeMaxDynamicSharedMemorySize, SMEM_BYTES);

    bn_partial_kernel<<<256, 256>>>(x);
    bn_finalize_kernel<<<1, DD>>>(ig, ib);
    bn_apply_kernel<<<BB * DD / 4 / 256, 256>>>(x);

    const int g128 = (HH * DD + 255) / 256, g192 = (HH * OUTF + 255) / 256;
    for (int s = 0; s < NSTEP; s++) {
        if (s < NSTEP - 1) {
            wsplit_kernel<<<g128, 256>>>(eW0 + (size_t)s * HH * DD,  p_eW0s + (size_t)s * HH * 3 * DD,  DD);
            wsplit_kernel<<<g192, 256>>>(eW1 + (size_t)s * HH * OUTF, p_eW1s + (size_t)s * HH * 3 * OUTF, OUTF);
        }
        wsplit_kernel<<<g128, 256>>>(dW0 + (size_t)s * HH * DD,  p_dW0s + (size_t)s * HH * 3 * DD,  DD);
        wsplit_kernel<<<g192, 256>>>(dW1 + (size_t)s * HH * OUTF, p_dW1s + (size_t)s * HH * 3 * OUTF, OUTF);
    }

    dim3 g3(3, BB / 128);     // full 384 cols
    dim3 g2(2, BB / 128);     // enc GLU1: only cols 128..383 (u >= 64)  [att uses enc[:,64:]]
    dim3 g1(1, BB / 128);     // dec GLU1: only cols 0..127   (u < 64)   [out uses dec[:,:64]]
    for (int s = 0; s < NSTEP; s++) {
        sparsemax_kernel<<<SMBLK, 256>>>(s);
        if (s < NSTEP - 1) {   // enc path is dead at the last step
            gemm_glu_kernel<3 * DD, true><<<g3, 256, SMEM_BYTES>>>(
                p_ax, p_eW0s + (size_t)s * HH * 3 * DD, eg0 + s * HH, eb0 + s * HH,
                nullptr, p_as, 0);
            gemm_glu_kernel<3 * OUTF, false><<<g2, 256, SMEM_BYTES>>>(
                p_as, p_eW1s + (size_t)s * HH * 3 * OUTF, eg1 + s * HH, eb1 + s * HH,
                p_enc, nullptr, 1);
        }
        gemm_glu_kernel<3 * DD, true><<<g3, 256, SMEM_BYTES>>>(
            p_ax, p_dW0s + (size_t)s * HH * 3 * DD, dg0 + s * HH, db0 + s * HH,
            nullptr, p_as, 0);
        gemm_glu_kernel<3 * OUTF, false><<<g1, 256, SMEM_BYTES>>>(
            p_as, p_dW1s + (size_t)s * HH * 3 * OUTF, dg1 + s * HH, db1 + s * HH,
            p_a, nullptr, 0);
        epilogue_kernel<<<256, 256>>>(p_a, p_enc, out + (size_t)s * BB * NDOUT,
                                      (s < NSTEP - 1) ? 1 : 0);
    }
    if (out_size > BB * NDOUT * NSTEP) {
        loss_finalize_kernel<<<1, 256>>>(out + (size_t)BB * NDOUT * NSTEP);
    }
}

// round 7
// speedup vs baseline: 4.1360x; 1.6503x over previous
#include <cuda_runtime.h>
#include <cuda_fp16.h>
#include <cstdint>

// ---------------- problem constants ----------------
constexpr int BB     = 32768;   // batch
constexpr int DD     = 128;     // input dim
constexpr int OUTF   = 192;     // n_d + n_a
constexpr int HH     = 384;     // 2*OUTF
constexpr int NSTEP  = 3;
constexpr int NDOUT  = 64;      // n_d
constexpr int SMBLK  = 1024;    // sparsemax blocks (32 rows each)
#define EPS_BN 1e-5f

// ---------------- scratch (device globals: allocation-free) ----------------
__device__ float g_xbn[BB * DD];
__device__ float g_M[BB * DD];
__device__ float g_enc[BB * OUTF];          // sigmoid(enc GLU out); only cols 64..191 written/used
__device__ float g_bnpart[256 * 2 * DD];
__device__ float g_bnscale[DD];
__device__ float g_bnshift[DD];
__device__ float g_losspart[NSTEP * SMBLK];

// fp16 activations (single plane)
__device__ __align__(128) __half g_ax[BB * DD];     // masked_x
__device__ __align__(128) __half g_as[BB * OUTF];   // GLU0 out

// fp16 2-plane PERMUTED weights: row layout [Wh(K) | Wl(K)]; row perm: n<192->2n else 2(n-192)+1
__device__ __align__(128) __half g_eW0s[NSTEP * HH * 2 * DD];
__device__ __align__(128) __half g_eW1s[NSTEP * HH * 2 * OUTF];
__device__ __align__(128) __half g_dW0s[NSTEP * HH * 2 * DD];
__device__ __align__(128) __half g_dW1s[NSTEP * HH * 2 * OUTF];

// ---------------- mma / ldmatrix / cp.async primitives ----------------
__device__ __forceinline__ void ldsm4(unsigned* r, const void* p) {
    unsigned a = (unsigned)__cvta_generic_to_shared(p);
    asm volatile("ldmatrix.sync.aligned.m8n8.x4.shared.b16 {%0,%1,%2,%3}, [%4];"
                 : "=r"(r[0]), "=r"(r[1]), "=r"(r[2]), "=r"(r[3]) : "r"(a));
}
__device__ __forceinline__ void mma16816(float* d, const unsigned* a, unsigned b0, unsigned b1) {
    asm volatile(
        "mma.sync.aligned.m16n8k16.row.col.f32.f16.f16.f32 "
        "{%0,%1,%2,%3}, {%4,%5,%6,%7}, {%8,%9}, {%0,%1,%2,%3};"
        : "+f"(d[0]), "+f"(d[1]), "+f"(d[2]), "+f"(d[3])
        : "r"(a[0]), "r"(a[1]), "r"(a[2]), "r"(a[3]), "r"(b0), "r"(b1));
}
__device__ __forceinline__ void cp16(void* sdst, const void* gsrc) {
    unsigned a = (unsigned)__cvta_generic_to_shared(sdst);
    asm volatile("cp.async.cg.shared.global [%0], [%1], 16;" :: "r"(a), "l"(gsrc));
}
__device__ __forceinline__ void cp_commit() {
    asm volatile("cp.async.commit_group;" ::: "memory");
}
__device__ __forceinline__ void cp_wait0() {
    asm volatile("cp.async.wait_group 0;" ::: "memory");
}

// ---------------- smem plan for fused kernel (temporally reused) ----------
// mainloop: Asm/Bhm/Blm each [2][128][40] fp16 = 10240B x3 x2buf = 61440B
// epilogue: stage 128 x 132 fp32 = 67584B (reuses same region) + sc/sh
constexpr int STAGE_LD   = 132;
constexpr int SM_SC_OFF  = 128 * STAGE_LD * 4;          // 67584
constexpr int SM_SH_OFF  = SM_SC_OFF + 512;
constexpr int SMEM_BYTES = SM_SH_OFF + 512;             // 68608

// ---------------- BN stats ----------------
__global__ void bn_partial_kernel(const float* __restrict__ x) {
    __shared__ float ss[256], sq[256];
    int t = threadIdx.x, blk = blockIdx.x;
    int col = t & 127, half = t >> 7;
    const float* xp = x + ((size_t)blk * 128 + half * 64) * DD + col;
    float s = 0.f, q = 0.f;
#pragma unroll 8
    for (int r = 0; r < 64; r++) { float v = xp[(size_t)r * DD]; s += v; q += v * v; }
    ss[t] = s; sq[t] = q;
    __syncthreads();
    if (t < 128) {
        g_bnpart[(blk * 2 + 0) * DD + t] = ss[t] + ss[t + 128];
        g_bnpart[(blk * 2 + 1) * DD + t] = sq[t] + sq[t + 128];
    }
}

__global__ void bn_finalize_kernel(const float* __restrict__ gam, const float* __restrict__ bet) {
    int c = threadIdx.x;
    float s = 0.f, q = 0.f;
    for (int b = 0; b < 256; b++) {
        s += g_bnpart[(b * 2 + 0) * DD + c];
        q += g_bnpart[(b * 2 + 1) * DD + c];
    }
    float mean = s / (float)BB;
    float var  = q / (float)BB - mean * mean;
    float inv  = 1.f / sqrtf(var + EPS_BN);
    float sc   = gam[c] * inv;
    g_bnscale[c] = sc;
    g_bnshift[c] = bet[c] - mean * sc;
}

__global__ void bn_apply_kernel(const float* __restrict__ x) {
    int i = blockIdx.x * blockDim.x + threadIdx.x;
    if (i >= BB * DD / 4) return;
    float4 v = ((const float4*)x)[i];
    int c = (i & 31) * 4;
    v.x = v.x * g_bnscale[c + 0] + g_bnshift[c + 0];
    v.y = v.y * g_bnscale[c + 1] + g_bnshift[c + 1];
    v.z = v.z * g_bnscale[c + 2] + g_bnshift[c + 2];
    v.w = v.w * g_bnscale[c + 3] + g_bnshift[c + 3];
    ((float4*)g_xbn)[i] = v;
}

// ---------------- merged weight split (ONE launch for all 10 matrices) -------
// grid.y = step*4 + which; which: 0=eW0 1=eW1 2=dW0 3=dW1. Skips dead enc @ s=2.
// src [384,K] fp32 -> dst [384 perm, 2K] fp16 [Wh|Wl]; perm: n<192->2n else 2(n-192)+1
__global__ void wsplit_all_kernel(const float* __restrict__ eW0, const float* __restrict__ eW1,
                                  const float* __restrict__ dW0, const float* __restrict__ dW1,
                                  __half* oe0, __half* oe1, __half* od0, __half* od1) {
    int y = blockIdx.y;
    int s = y >> 2, which = y & 3;
    if (s == NSTEP - 1 && which < 2) return;   // enc weights dead at last step
    int K = (which & 1) ? OUTF : DD;
    int i = blockIdx.x * 256 + threadIdx.x;
    if (i >= HH * K) return;
    const float* src = (which == 0 ? eW0 : which == 1 ? eW1 : which == 2 ? dW0 : dW1)
                       + (size_t)s * HH * K;
    __half* dst = (which == 0 ? oe0 : which == 1 ? oe1 : which == 2 ? od0 : od1)
                  + (size_t)s * HH * 2 * K;
    int n = i / K, k = i - n * K;
    int perm = (n < OUTF) ? (2 * n) : (2 * (n - OUTF) + 1);
    float w = src[i];
    __half h = __float2half(w);
    __half l = __float2half(w - __half2float(h));
    dst[(size_t)perm * 2 * K + k]     = h;
    dst[(size_t)perm * 2 * K + K + k] = l;
}

// ---------------- sparsemax (fused att-gen) + mask + loss + fp16 write -------
__global__ void sparsemax_kernel(int step) {
    __shared__ float wl[8];
    int t = threadIdx.x, lane = t & 31, w = t >> 5, blk = blockIdx.x;
    float acc = 0.f;
    for (int rr = 0; rr < 4; rr++) {
        size_t row = (size_t)blk * 32 + w * 4 + rr;
        const float* xp = g_xbn + row * DD;
        float* Mp = g_M + row * DD;
        __half* axp = g_ax + row * DD;
        if (step == 0) {
            // att == 1 -> sparsemax uniform: M = 1/128 exactly
            const float m = 1.f / 128.f;
#pragma unroll
            for (int i = 0; i < 4; i++) {
                int c = lane + 32 * i;
                Mp[c] = m;
                axp[c] = __float2half(m * xp[c]);
            }
            acc += logf(m + 1e-10f);   // row sum of M*log(M+eps) = log(m+eps)
            continue;
        }
        // att = 1.3 * sigmoid(enc) * (1 - Mprev);  g_enc stores sigmoid already
        const float* ep = g_enc + row * OUTF + NDOUT;
        float z0, z1, z2, z3;
        {
            float m0_ = Mp[lane], m1_ = Mp[lane + 32], m2_ = Mp[lane + 64], m3_ = Mp[lane + 96];
            z0 = 1.3f * ep[lane]      * (1.f - m0_);
            z1 = 1.3f * ep[lane + 32] * (1.f - m1_);
            z2 = 1.3f * ep[lane + 64] * (1.f - m2_);
            z3 = 1.3f * ep[lane + 96] * (1.f - m3_);
        }
        float mx = fmaxf(fmaxf(z0, z1), fmaxf(z2, z3));
#pragma unroll
        for (int o = 16; o; o >>= 1) mx = fmaxf(mx, __shfl_xor_sync(0xffffffffu, mx, o));
        z0 -= mx; z1 -= mx; z2 -= mx; z3 -= mx;
        float sm = z0 + z1 + z2 + z3;
#pragma unroll
        for (int o = 16; o; o >>= 1) sm += __shfl_xor_sync(0xffffffffu, sm, o);
        float tau = (sm - 1.f) * (1.f / 128.f);
        int cnt = 128;
        for (int it = 0; it < 64; it++) {
            float s = 0.f; int c = 0;
            if (z0 > tau) { s += z0; c++; }
            if (z1 > tau) { s += z1; c++; }
            if (z2 > tau) { s += z2; c++; }
            if (z3 > tau) { s += z3; c++; }
#pragma unroll
            for (int o = 16; o; o >>= 1) {
                s += __shfl_xor_sync(0xffffffffu, s, o);
                c += __shfl_xor_sync(0xffffffffu, c, o);
            }
            if (c == cnt) break;
            cnt = c; tau = (s - 1.f) / (float)c;
        }
        float m[4] = {fmaxf(z0 - tau, 0.f), fmaxf(z1 - tau, 0.f),
                      fmaxf(z2 - tau, 0.f), fmaxf(z3 - tau, 0.f)};
        float rl = 0.f;
#pragma unroll
        for (int i = 0; i < 4; i++) {
            int c = lane + 32 * i;
            Mp[c] = m[i];
            axp[c] = __float2half(m[i] * xp[c]);
            rl += m[i] * logf(m[i] + 1e-10f);
        }
#pragma unroll
        for (int o = 16; o; o >>= 1) rl += __shfl_xor_sync(0xffffffffu, rl, o);
        acc += rl;
    }
    if (lane == 0) wl[w] = acc;
    __syncthreads();
    if (t == 0) {
        float s = 0.f;
        for (int i = 0; i < 8; i++) s += wl[i];
        g_losspart[step * SMBLK + blk] = s;
    }
}

// ---------------- fused fp16 mma.sync GEMM + GhostBN + GLU -------------------
// C = A(fp16)[128 rows] x (Wh + Wl)^T[128 perm cols]; per-col BN over the CTA's
// 128 rows (== one GBN chunk); GLU on adjacent col pairs.
// MODE 0: write fp16 activation (GLU0 out). MODE 1: write sigmoid to g_enc.
// MODE 2: write sigmoid to final output (stride NDOUT).
template <int K, int MODE>
__global__ __launch_bounds__(256, 2) void gemm_glu_kernel(
        const __half* __restrict__ A,
        const __half* __restrict__ W2,
        const float* __restrict__ gam, const float* __restrict__ bet,
        float* __restrict__ outp, __half* __restrict__ outs,
        int nxoff) {
    extern __shared__ __align__(16) char smem[];
    __half* Asm = (__half*)smem;              // [2][128][40]
    __half* Bhm = Asm + 2 * 128 * 40;
    __half* Blm = Asm + 4 * 128 * 40;
    constexpr int T = K / 32;

    const int t = threadIdx.x;
    const int m0 = blockIdx.y * 128;
    const int nx = blockIdx.x + nxoff;
    const int n0 = nx * 128;
    const int lrow = t >> 1;
    const int lcol = (t & 1) * 16;

    const __half* Ag = A  + (size_t)(m0 + lrow) * K + lcol;
    const __half* Wh = W2 + (size_t)(n0 + lrow) * (2 * K) + lcol;
    const __half* Wl = Wh + K;

    const int warp = t >> 5, lane = t & 31;
    const int wm = warp >> 1, wn = warp & 1;
    const int lr = lane & 15, lc = (lane >> 4) * 8;
    const int so = lrow * 40 + lcol;          // smem store offset (elements)

    float d[2][8][4];
#pragma unroll
    for (int i = 0; i < 2; i++)
#pragma unroll
        for (int j = 0; j < 8; j++)
#pragma unroll
            for (int k = 0; k < 4; k++) d[i][j][k] = 0.f;

    // prologue: async-fill buffer 0
    cp16(&Asm[so], Ag);      cp16(&Asm[so + 8], Ag + 8);
    cp16(&Bhm[so], Wh);      cp16(&Bhm[so + 8], Wh + 8);
    cp16(&Blm[so], Wl);      cp16(&Blm[so + 8], Wl + 8);
    cp_commit(); cp_wait0();
    __syncthreads();

    for (int kt = 0; kt < T; kt++) {
        const int bo = (kt & 1) * 5120;
        if (kt + 1 < T) {
            const int no = ((kt + 1) & 1) * 5120, off = (kt + 1) * 32;
            cp16(&Asm[no + so], Ag + off);  cp16(&Asm[no + so + 8], Ag + off + 8);
            cp16(&Bhm[no + so], Wh + off);  cp16(&Bhm[no + so + 8], Wh + off + 8);
            cp16(&Blm[no + so], Wl + off);  cp16(&Blm[no + so + 8], Wl + off + 8);
            cp_commit();
        }
#pragma unroll
        for (int ks = 0; ks < 2; ks++) {
            const int krow = ks * 16 + lc;
            unsigned afr[2][4], bfr[4][4];
#pragma unroll
            for (int mf = 0; mf < 2; mf++)
                ldsm4(afr[mf], &Asm[bo + (wm * 32 + mf * 16 + lr) * 40 + krow]);
#pragma unroll
            for (int nb = 0; nb < 4; nb++)
                ldsm4(bfr[nb], &Bhm[bo + (wn * 64 + nb * 16 + lr) * 40 + krow]);
#pragma unroll
            for (int mf = 0; mf < 2; mf++)
#pragma unroll
                for (int n8 = 0; n8 < 8; n8++)
                    mma16816(d[mf][n8], afr[mf], bfr[n8 >> 1][n8 & 1], bfr[n8 >> 1][(n8 & 1) + 2]);
#pragma unroll
            for (int nb = 0; nb < 4; nb++)
                ldsm4(bfr[nb], &Blm[bo + (wn * 64 + nb * 16 + lr) * 40 + krow]);
#pragma unroll
            for (int mf = 0; mf < 2; mf++)
#pragma unroll
                for (int n8 = 0; n8 < 8; n8++)
                    mma16816(d[mf][n8], afr[mf], bfr[n8 >> 1][n8 & 1], bfr[n8 >> 1][(n8 & 1) + 2]);
        }
        if (kt + 1 < T) { cp_wait0(); __syncthreads(); }
    }
    __syncthreads();   // mainloop done; smem free for stage

    // --- stage accumulators as fp32 [128][132] ---
    float* stage = (float*)smem;
#pragma unroll
    for (int mf = 0; mf < 2; mf++)
#pragma unroll
        for (int n8 = 0; n8 < 8; n8++) {
            int r_ = wm * 32 + mf * 16 + (lane >> 2);
            int c_ = wn * 64 + n8 * 8 + (lane & 3) * 2;
            stage[r_ * STAGE_LD + c_]           = d[mf][n8][0];
            stage[r_ * STAGE_LD + c_ + 1]       = d[mf][n8][1];
            stage[(r_ + 8) * STAGE_LD + c_]     = d[mf][n8][2];
            stage[(r_ + 8) * STAGE_LD + c_ + 1] = d[mf][n8][3];
        }
    __syncthreads();

    // --- GhostBN per column ---
    float* scp = (float*)(smem + SM_SC_OFF);
    float* shp = (float*)(smem + SM_SH_OFF);
    if (t < 128) {
        float s = 0.f, q = 0.f;
#pragma unroll 4
        for (int r = 0; r < 128; r++) {
            float v = stage[r * STAGE_LD + t];
            s += v; q += v * v;
        }
        float mean = s * (1.f / 128.f);
        float var  = q * (1.f / 128.f) - mean * mean;
        int ncol = n0 + t;
        int u = ncol >> 1, p = ncol & 1;
        int orig = u + p * OUTF;
        float scale = gam[orig] / sqrtf(var + EPS_BN);
        scp[t] = scale;
        shp[t] = bet[orig] - mean * scale;
    }
    __syncthreads();

    // --- GLU + mode-specific write ---
    for (int idx = t; idx < 128 * 64; idx += 256) {
        int r = idx >> 6, up = idx & 63;
        float a = stage[r * STAGE_LD + 2 * up]     * scp[2 * up]     + shp[2 * up];
        float g = stage[r * STAGE_LD + 2 * up + 1] * scp[2 * up + 1] + shp[2 * up + 1];
        float v = a * (1.f / (1.f + expf(-g)));
        int u = nx * 64 + up;
        size_t row = (size_t)(m0 + r);
        if (MODE == 0) {
            outs[row * OUTF + u] = __float2half(v);
        } else {
            float sig = 1.f / (1.f + expf(-v));
            if (MODE == 1) outp[row * OUTF + u] = sig;       // enc: sigmoid stored
            else           outp[row * NDOUT + u] = sig;      // dec: final output
        }
    }
}

// ---------------- loss finalize ----------------
__global__ void loss_finalize_kernel(float* __restrict__ outp) {
    __shared__ float s[256];
    int t = threadIdx.x;
    float a = 0.f;
    for (int i = t; i < NSTEP * SMBLK; i += 256) a += g_losspart[i];
    s[t] = a;
    __syncthreads();
    for (int o = 128; o; o >>= 1) {
        if (t < o) s[t] += s[t + o];
        __syncthreads();
    }
    if (t == 0) outp[0] = s[0] / ((float)BB * (float)NSTEP);
}

// ---------------- launch ----------------
extern "C" void kernel_launch(void* const* d_in, const int* in_sizes, int n_in,
                              void* d_out, int out_size) {
    (void)in_sizes; (void)n_in;
    const float* x   = (const float*)d_in[0];
    const float* ig  = (const float*)d_in[1];
    const float* ib  = (const float*)d_in[2];
    const float* eW0 = (const float*)d_in[3];
    const float* eg0 = (const float*)d_in[4];
    const float* eb0 = (const float*)d_in[5];
    const float* eW1 = (const float*)d_in[6];
    const float* eg1 = (const float*)d_in[7];
    const float* eb1 = (const float*)d_in[8];
    const float* dW0 = (const float*)d_in[9];
    const float* dg0 = (const float*)d_in[10];
    const float* db0 = (const float*)d_in[11];
    const float* dW1 = (const float*)d_in[12];
    const float* dg1 = (const float*)d_in[13];
    const float* db1 = (const float*)d_in[14];
    float* out = (float*)d_out;

    float* p_enc;
    __half *p_ax, *p_as, *p_eW0s, *p_eW1s, *p_dW0s, *p_dW1s;
    cudaGetSymbolAddress((void**)&p_enc, g_enc);
    cudaGetSymbolAddress((void**)&p_ax, g_ax);
    cudaGetSymbolAddress((void**)&p_as, g_as);
    cudaGetSymbolAddress((void**)&p_eW0s, g_eW0s);
    cudaGetSymbolAddress((void**)&p_eW1s, g_eW1s);
    cudaGetSymbolAddress((void**)&p_dW0s, g_dW0s);
    cudaGetSymbolAddress((void**)&p_dW1s, g_dW1s);

    cudaFuncSetAttribute(gemm_glu_kernel<DD, 0>,
                         cudaFuncAttributeMaxDynamicSharedMemorySize, SMEM_BYTES);
    cudaFuncSetAttribute(gemm_glu_kernel<OUTF, 1>,
                         cudaFuncAttributeMaxDynamicSharedMemorySize, SMEM_BYTES);
    cudaFuncSetAttribute(gemm_glu_kernel<OUTF, 2>,
                         cudaFuncAttributeMaxDynamicSharedMemorySize, SMEM_BYTES);

    bn_partial_kernel<<<256, 256>>>(x);
    bn_finalize_kernel<<<1, DD>>>(ig, ib);
    bn_apply_kernel<<<BB * DD / 4 / 256, 256>>>(x);

    {
        dim3 gw((HH * OUTF + 255) / 256, NSTEP * 4);
        wsplit_all_kernel<<<gw, 256>>>(eW0, eW1, dW0, dW1, p_eW0s, p_eW1s, p_dW0s, p_dW1s);
    }

    dim3 g3(3, BB / 128);     // GLU0: full 384 perm cols
    dim3 g2(2, BB / 128);     // enc GLU1: perm cols 128..383 (u >= 64)
    dim3 g1(1, BB / 128);     // dec GLU1: perm cols 0..127   (u < 64)
    for (int s = 0; s < NSTEP; s++) {
        sparsemax_kernel<<<SMBLK, 256>>>(s);
        if (s < NSTEP - 1) {   // enc path dead at the last step
            gemm_glu_kernel<DD, 0><<<g3, 256, SMEM_BYTES>>>(
                p_ax, p_eW0s + (size_t)s * HH * 2 * DD, eg0 + s * HH, eb0 + s * HH,
                nullptr, p_as, 0);
            gemm_glu_kernel<OUTF, 1><<<g2, 256, SMEM_BYTES>>>(
                p_as, p_eW1s + (size_t)s * HH * 2 * OUTF, eg1 + s * HH, eb1 + s * HH,
                p_enc, nullptr, 1);
        }
        gemm_glu_kernel<DD, 0><<<g3, 256, SMEM_BYTES>>>(
            p_ax, p_dW0s + (size_t)s * HH * 2 * DD, dg0 + s * HH, db0 + s * HH,
            nullptr, p_as, 0);
        gemm_glu_kernel<OUTF, 2><<<g1, 256, SMEM_BYTES>>>(
            p_as, p_dW1s + (size_t)s * HH * 2 * OUTF, dg1 + s * HH, db1 + s * HH,
            out + (size_t)s * BB * NDOUT, nullptr, 0);
    }
    if (out_size > BB * NDOUT * NSTEP) {
        loss_finalize_kernel<<<1, 256>>>(out + (size_t)BB * NDOUT * NSTEP);
    }
}

// round 8
// speedup vs baseline: 5.2538x; 1.2703x over previous
#include <cuda_runtime.h>
#include <cuda_fp16.h>
#include <cstdint>

// ---------------- problem constants ----------------
constexpr int BB     = 32768;   // batch
constexpr int DD     = 128;     // input dim
constexpr int OUTF   = 192;     // n_d + n_a
constexpr int HH     = 384;     // 2*OUTF
constexpr int NSTEP  = 3;
constexpr int NDOUT  = 64;      // n_d
constexpr int SMBLK  = 1024;    // sparsemax blocks (32 rows each)
#define EPS_BN 1e-5f

// ---------------- scratch (device globals: allocation-free) ----------------
__device__ float g_xbn[BB * DD];
__device__ float g_M[BB * DD];
__device__ float g_enc[BB * OUTF];          // sigmoid(enc GLU out); only cols 64..191 written/used
__device__ float g_bnpart[256 * 2 * DD];
__device__ float g_bnscale[DD];
__device__ float g_bnshift[DD];
__device__ float g_losspart[NSTEP * SMBLK];

// fp16 activations
__device__ __align__(128) __half g_ax[BB * DD];      // masked_x
__device__ __align__(128) __half g_ase[BB * OUTF];   // enc GLU0 out
__device__ __align__(128) __half g_asd[BB * OUTF];   // dec GLU0 out

// fp16 PERMUTED weights (single plane); row perm: n<192->2n else 2(n-192)+1
__device__ __align__(128) __half g_eW0s[NSTEP * HH * DD];
__device__ __align__(128) __half g_eW1s[NSTEP * HH * OUTF];
__device__ __align__(128) __half g_dW0s[NSTEP * HH * DD];
__device__ __align__(128) __half g_dW1s[NSTEP * HH * OUTF];

// ---------------- mma / ldmatrix / cp.async primitives ----------------
__device__ __forceinline__ void ldsm4(unsigned* r, const void* p) {
    unsigned a = (unsigned)__cvta_generic_to_shared(p);
    asm volatile("ldmatrix.sync.aligned.m8n8.x4.shared.b16 {%0,%1,%2,%3}, [%4];"
                 : "=r"(r[0]), "=r"(r[1]), "=r"(r[2]), "=r"(r[3]) : "r"(a));
}
__device__ __forceinline__ void mma16816(float* d, const unsigned* a, unsigned b0, unsigned b1) {
    asm volatile(
        "mma.sync.aligned.m16n8k16.row.col.f32.f16.f16.f32 "
        "{%0,%1,%2,%3}, {%4,%5,%6,%7}, {%8,%9}, {%0,%1,%2,%3};"
        : "+f"(d[0]), "+f"(d[1]), "+f"(d[2]), "+f"(d[3])
        : "r"(a[0]), "r"(a[1]), "r"(a[2]), "r"(a[3]), "r"(b0), "r"(b1));
}
__device__ __forceinline__ void cp16(void* sdst, const void* gsrc) {
    unsigned a = (unsigned)__cvta_generic_to_shared(sdst);
    asm volatile("cp.async.cg.shared.global [%0], [%1], 16;" :: "r"(a), "l"(gsrc));
}
__device__ __forceinline__ void cp_commit() {
    asm volatile("cp.async.commit_group;" ::: "memory");
}
__device__ __forceinline__ void cp_wait0() {
    asm volatile("cp.async.wait_group 0;" ::: "memory");
}

// ---------------- smem plan (temporally reused) ----------
// mainloop: Asm/Bsm each [2][128][40] fp16 = 10240B x2 x... = 40960B total
// epilogue: stage 128 x 132 fp32 = 67584B (reuses same region) + sc/sh
constexpr int STAGE_LD   = 132;
constexpr int SM_SC_OFF  = 128 * STAGE_LD * 4;          // 67584
constexpr int SM_SH_OFF  = SM_SC_OFF + 512;
constexpr int SMEM_BYTES = SM_SH_OFF + 512;             // 68608

// ---------------- BN stats ----------------
__global__ void bn_partial_kernel(const float* __restrict__ x) {
    __shared__ float ss[256], sq[256];
    int t = threadIdx.x, blk = blockIdx.x;
    int col = t & 127, half = t >> 7;
    const float* xp = x + ((size_t)blk * 128 + half * 64) * DD + col;
    float s = 0.f, q = 0.f;
#pragma unroll 8
    for (int r = 0; r < 64; r++) { float v = xp[(size_t)r * DD]; s += v; q += v * v; }
    ss[t] = s; sq[t] = q;
    __syncthreads();
    if (t < 128) {
        g_bnpart[(blk * 2 + 0) * DD + t] = ss[t] + ss[t + 128];
        g_bnpart[(blk * 2 + 1) * DD + t] = sq[t] + sq[t + 128];
    }
}

__global__ void bn_finalize_kernel(const float* __restrict__ gam, const float* __restrict__ bet) {
    int c = threadIdx.x;
    float s = 0.f, q = 0.f;
    for (int b = 0; b < 256; b++) {
        s += g_bnpart[(b * 2 + 0) * DD + c];
        q += g_bnpart[(b * 2 + 1) * DD + c];
    }
    float mean = s / (float)BB;
    float var  = q / (float)BB - mean * mean;
    float inv  = 1.f / sqrtf(var + EPS_BN);
    float sc   = gam[c] * inv;
    g_bnscale[c] = sc;
    g_bnshift[c] = bet[c] - mean * sc;
}

__global__ void bn_apply_kernel(const float* __restrict__ x) {
    int i = blockIdx.x * blockDim.x + threadIdx.x;
    if (i >= BB * DD / 4) return;
    float4 v = ((const float4*)x)[i];
    int c = (i & 31) * 4;
    v.x = v.x * g_bnscale[c + 0] + g_bnshift[c + 0];
    v.y = v.y * g_bnscale[c + 1] + g_bnshift[c + 1];
    v.z = v.z * g_bnscale[c + 2] + g_bnshift[c + 2];
    v.w = v.w * g_bnscale[c + 3] + g_bnshift[c + 3];
    ((float4*)g_xbn)[i] = v;
}

// ---------------- merged weight convert+permute (ONE launch, all 10) --------
// grid.y = step*4 + which; which: 0=eW0 1=eW1 2=dW0 3=dW1. Skips dead enc @ s=2.
// src [384,K] fp32 -> dst [384 perm, K] fp16; perm: n<192->2n else 2(n-192)+1
__global__ void wsplit_all_kernel(const float* __restrict__ eW0, const float* __restrict__ eW1,
                                  const float* __restrict__ dW0, const float* __restrict__ dW1,
                                  __half* oe0, __half* oe1, __half* od0, __half* od1) {
    int y = blockIdx.y;
    int s = y >> 2, which = y & 3;
    if (s == NSTEP - 1 && which < 2) return;   // enc weights dead at last step
    int K = (which & 1) ? OUTF : DD;
    int i = blockIdx.x * 256 + threadIdx.x;
    if (i >= HH * K) return;
    const float* src = (which == 0 ? eW0 : which == 1 ? eW1 : which == 2 ? dW0 : dW1)
                       + (size_t)s * HH * K;
    __half* dst = (which == 0 ? oe0 : which == 1 ? oe1 : which == 2 ? od0 : od1)
                  + (size_t)s * HH * K;
    int n = i / K, k = i - n * K;
    int perm = (n < OUTF) ? (2 * n) : (2 * (n - OUTF) + 1);
    dst[(size_t)perm * K + k] = __float2half(src[i]);
}

// ---------------- sparsemax (fused att-gen) + mask + loss + fp16 write -------
__global__ void sparsemax_kernel(int step) {
    __shared__ float wl[8];
    int t = threadIdx.x, lane = t & 31, w = t >> 5, blk = blockIdx.x;
    float acc = 0.f;
    for (int rr = 0; rr < 4; rr++) {
        size_t row = (size_t)blk * 32 + w * 4 + rr;
        const float* xp = g_xbn + row * DD;
        float* Mp = g_M + row * DD;
        __half* axp = g_ax + row * DD;
        if (step == 0) {
            const float m = 1.f / 128.f;
#pragma unroll
            for (int i = 0; i < 4; i++) {
                int c = lane + 32 * i;
                Mp[c] = m;
                axp[c] = __float2half(m * xp[c]);
            }
            acc += logf(m + 1e-10f);
            continue;
        }
        const float* ep = g_enc + row * OUTF + NDOUT;
        float z0, z1, z2, z3;
        {
            float m0_ = Mp[lane], m1_ = Mp[lane + 32], m2_ = Mp[lane + 64], m3_ = Mp[lane + 96];
            z0 = 1.3f * ep[lane]      * (1.f - m0_);
            z1 = 1.3f * ep[lane + 32] * (1.f - m1_);
            z2 = 1.3f * ep[lane + 64] * (1.f - m2_);
            z3 = 1.3f * ep[lane + 96] * (1.f - m3_);
        }
        float mx = fmaxf(fmaxf(z0, z1), fmaxf(z2, z3));
#pragma unroll
        for (int o = 16; o; o >>= 1) mx = fmaxf(mx, __shfl_xor_sync(0xffffffffu, mx, o));
        z0 -= mx; z1 -= mx; z2 -= mx; z3 -= mx;
        float sm = z0 + z1 + z2 + z3;
#pragma unroll
        for (int o = 16; o; o >>= 1) sm += __shfl_xor_sync(0xffffffffu, sm, o);
        float tau = (sm - 1.f) * (1.f / 128.f);
        int cnt = 128;
        for (int it = 0; it < 64; it++) {
            float s = 0.f; int c = 0;
            if (z0 > tau) { s += z0; c++; }
            if (z1 > tau) { s += z1; c++; }
            if (z2 > tau) { s += z2; c++; }
            if (z3 > tau) { s += z3; c++; }
#pragma unroll
            for (int o = 16; o; o >>= 1) {
                s += __shfl_xor_sync(0xffffffffu, s, o);
                c += __shfl_xor_sync(0xffffffffu, c, o);
            }
            if (c == cnt) break;
            cnt = c; tau = (s - 1.f) / (float)c;
        }
        float m[4] = {fmaxf(z0 - tau, 0.f), fmaxf(z1 - tau, 0.f),
                      fmaxf(z2 - tau, 0.f), fmaxf(z3 - tau, 0.f)};
        float rl = 0.f;
#pragma unroll
        for (int i = 0; i < 4; i++) {
            int c = lane + 32 * i;
            Mp[c] = m[i];
            axp[c] = __float2half(m[i] * xp[c]);
            rl += m[i] * logf(m[i] + 1e-10f);
        }
#pragma unroll
        for (int o = 16; o; o >>= 1) rl += __shfl_xor_sync(0xffffffffu, rl, o);
        acc += rl;
    }
    if (lane == 0) wl[w] = acc;
    __syncthreads();
    if (t == 0) {
        float s = 0.f;
        for (int i = 0; i < 8; i++) s += wl[i];
        g_losspart[step * SMBLK + blk] = s;
    }
}

// ---------------- fused fp16 GEMM + GhostBN + GLU, enc+dec merged ------------
// GLU1=false (GLU0): blockIdx.x < enc_blocks -> enc (W=We, out=h_oute),
//                    else dec (nx -= enc_blocks, W=Wd, out=h_outd); fp16 write.
// GLU1=true  (GLU1): blockIdx.x == 0 -> dec (out f_out, stride NDOUT, sigmoid),
//                    blockIdx.x >= 1 -> enc (out f_enc, stride OUTF, sigmoid).
template <int K, bool GLU1>
__global__ __launch_bounds__(256, 2) void gemm_glu_kernel(
        const __half* __restrict__ Ae, const __half* __restrict__ Ad,
        const __half* __restrict__ We, const __half* __restrict__ Wd,
        const float* __restrict__ eg, const float* __restrict__ eb,
        const float* __restrict__ dg, const float* __restrict__ db,
        __half* __restrict__ h_oute, __half* __restrict__ h_outd,
        float* __restrict__ f_enc, float* __restrict__ f_out,
        int enc_blocks) {
    extern __shared__ __align__(16) char smem[];
    __half* Asm = (__half*)smem;              // [2][128][40]
    __half* Bsm = Asm + 2 * 128 * 40;
    constexpr int T = K / 32;

    const int t = threadIdx.x;
    const int m0 = blockIdx.y * 128;
    bool is_enc; int nx;
    if (GLU1) { is_enc = (blockIdx.x > 0); nx = blockIdx.x; }
    else      { is_enc = ((int)blockIdx.x < enc_blocks); nx = is_enc ? blockIdx.x : blockIdx.x - enc_blocks; }
    const int n0 = nx * 128;
    const __half* A = is_enc ? Ae : Ad;
    const __half* W = is_enc ? We : Wd;
    const float* gam = is_enc ? eg : dg;
    const float* bet = is_enc ? eb : db;

    const int lrow = t >> 1;
    const int lcol = (t & 1) * 16;
    const __half* Ag = A + (size_t)(m0 + lrow) * K + lcol;
    const __half* Wg = W + (size_t)(n0 + lrow) * K + lcol;

    const int warp = t >> 5, lane = t & 31;
    const int wm = warp >> 1, wn = warp & 1;
    const int lr = lane & 15, lc = (lane >> 4) * 8;
    const int so = lrow * 40 + lcol;

    float d[2][8][4];
#pragma unroll
    for (int i = 0; i < 2; i++)
#pragma unroll
        for (int j = 0; j < 8; j++)
#pragma unroll
            for (int k = 0; k < 4; k++) d[i][j][k] = 0.f;

    cp16(&Asm[so], Ag);  cp16(&Asm[so + 8], Ag + 8);
    cp16(&Bsm[so], Wg);  cp16(&Bsm[so + 8], Wg + 8);
    cp_commit(); cp_wait0();
    __syncthreads();

    for (int kt = 0; kt < T; kt++) {
        const int bo = (kt & 1) * 5120;
        if (kt + 1 < T) {
            const int no = ((kt + 1) & 1) * 5120, off = (kt + 1) * 32;
            cp16(&Asm[no + so], Ag + off);  cp16(&Asm[no + so + 8], Ag + off + 8);
            cp16(&Bsm[no + so], Wg + off);  cp16(&Bsm[no + so + 8], Wg + off + 8);
            cp_commit();
        }
#pragma unroll
        for (int ks = 0; ks < 2; ks++) {
            const int krow = ks * 16 + lc;
            unsigned afr[2][4], bfr[4][4];
#pragma unroll
            for (int mf = 0; mf < 2; mf++)
                ldsm4(afr[mf], &Asm[bo + (wm * 32 + mf * 16 + lr) * 40 + krow]);
#pragma unroll
            for (int nb = 0; nb < 4; nb++)
                ldsm4(bfr[nb], &Bsm[bo + (wn * 64 + nb * 16 + lr) * 40 + krow]);
#pragma unroll
            for (int mf = 0; mf < 2; mf++)
#pragma unroll
                for (int n8 = 0; n8 < 8; n8++)
                    mma16816(d[mf][n8], afr[mf], bfr[n8 >> 1][n8 & 1], bfr[n8 >> 1][(n8 & 1) + 2]);
        }
        if (kt + 1 < T) { cp_wait0(); __syncthreads(); }
    }
    __syncthreads();   // mainloop done; smem free for stage

    // --- stage accumulators as fp32 [128][132] ---
    float* stage = (float*)smem;
#pragma unroll
    for (int mf = 0; mf < 2; mf++)
#pragma unroll
        for (int n8 = 0; n8 < 8; n8++) {
            int r_ = wm * 32 + mf * 16 + (lane >> 2);
            int c_ = wn * 64 + n8 * 8 + (lane & 3) * 2;
            stage[r_ * STAGE_LD + c_]           = d[mf][n8][0];
            stage[r_ * STAGE_LD + c_ + 1]       = d[mf][n8][1];
            stage[(r_ + 8) * STAGE_LD + c_]     = d[mf][n8][2];
            stage[(r_ + 8) * STAGE_LD + c_ + 1] = d[mf][n8][3];
        }
    __syncthreads();

    // --- GhostBN per column (this CTA's 128 rows == one GBN chunk) ---
    float* scp = (float*)(smem + SM_SC_OFF);
    float* shp = (float*)(smem + SM_SH_OFF);
    if (t < 128) {
        float s = 0.f, q = 0.f;
#pragma unroll 4
        for (int r = 0; r < 128; r++) {
            float v = stage[r * STAGE_LD + t];
            s += v; q += v * v;
        }
        float mean = s * (1.f / 128.f);
        float var  = q * (1.f / 128.f) - mean * mean;
        int ncol = n0 + t;
        int u = ncol >> 1, p = ncol & 1;
        int orig = u + p * OUTF;
        float scale = gam[orig] / sqrtf(var + EPS_BN);
        scp[t] = scale;
        shp[t] = bet[orig] - mean * scale;
    }
    __syncthreads();

    // --- GLU + write ---
    for (int idx = t; idx < 128 * 64; idx += 256) {
        int r = idx >> 6, up = idx & 63;
        float a = stage[r * STAGE_LD + 2 * up]     * scp[2 * up]     + shp[2 * up];
        float g = stage[r * STAGE_LD + 2 * up + 1] * scp[2 * up + 1] + shp[2 * up + 1];
        float v = a * (1.f / (1.f + expf(-g)));
        int u = nx * 64 + up;
        size_t row = (size_t)(m0 + r);
        if (!GLU1) {
            (is_enc ? h_oute : h_outd)[row * OUTF + u] = __float2half(v);
        } else {
            float sig = 1.f / (1.f + expf(-v));
            if (is_enc) f_enc[row * OUTF + u] = sig;
            else        f_out[row * NDOUT + u] = sig;
        }
    }
}

// ---------------- loss finalize ----------------
__global__ void loss_finalize_kernel(float* __restrict__ outp) {
    __shared__ float s[256];
    int t = threadIdx.x;
    float a = 0.f;
    for (int i = t; i < NSTEP * SMBLK; i += 256) a += g_losspart[i];
    s[t] = a;
    __syncthreads();
    for (int o = 128; o; o >>= 1) {
        if (t < o) s[t] += s[t + o];
        __syncthreads();
    }
    if (t == 0) outp[0] = s[0] / ((float)BB * (float)NSTEP);
}

// ---------------- launch ----------------
extern "C" void kernel_launch(void* const* d_in, const int* in_sizes, int n_in,
                              void* d_out, int out_size) {
    (void)in_sizes; (void)n_in;
    const float* x   = (const float*)d_in[0];
    const float* ig  = (const float*)d_in[1];
    const float* ib  = (const float*)d_in[2];
    const float* eW0 = (const float*)d_in[3];
    const float* eg0 = (const float*)d_in[4];
    const float* eb0 = (const float*)d_in[5];
    const float* eW1 = (const float*)d_in[6];
    const float* eg1 = (const float*)d_in[7];
    const float* eb1 = (const float*)d_in[8];
    const float* dW0 = (const float*)d_in[9];
    const float* dg0 = (const float*)d_in[10];
    const float* db0 = (const float*)d_in[11];
    const float* dW1 = (const float*)d_in[12];
    const float* dg1 = (const float*)d_in[13];
    const float* db1 = (const float*)d_in[14];
    float* out = (float*)d_out;

    float* p_enc;
    __half *p_ax, *p_ase, *p_asd, *p_eW0s, *p_eW1s, *p_dW0s, *p_dW1s;
    cudaGetSymbolAddress((void**)&p_enc, g_enc);
    cudaGetSymbolAddress((void**)&p_ax, g_ax);
    cudaGetSymbolAddress((void**)&p_ase, g_ase);
    cudaGetSymbolAddress((void**)&p_asd, g_asd);
    cudaGetSymbolAddress((void**)&p_eW0s, g_eW0s);
    cudaGetSymbolAddress((void**)&p_eW1s, g_eW1s);
    cudaGetSymbolAddress((void**)&p_dW0s, g_dW0s);
    cudaGetSymbolAddress((void**)&p_dW1s, g_dW1s);

    cudaFuncSetAttribute(gemm_glu_kernel<DD, false>,
                         cudaFuncAttributeMaxDynamicSharedMemorySize, SMEM_BYTES);
    cudaFuncSetAttribute(gemm_glu_kernel<OUTF, true>,
                         cudaFuncAttributeMaxDynamicSharedMemorySize, SMEM_BYTES);

    bn_partial_kernel<<<256, 256>>>(x);
    bn_finalize_kernel<<<1, DD>>>(ig, ib);
    bn_apply_kernel<<<BB * DD / 4 / 256, 256>>>(x);

    {
        dim3 gw((HH * OUTF + 255) / 256, NSTEP * 4);
        wsplit_all_kernel<<<gw, 256>>>(eW0, eW1, dW0, dW1, p_eW0s, p_eW1s, p_dW0s, p_dW1s);
    }

    for (int s = 0; s < NSTEP; s++) {
        sparsemax_kernel<<<SMBLK, 256>>>(s);
        const bool enc_live = (s < NSTEP - 1);
        // GLU0: enc (3 col-blocks, if live) + dec (3 col-blocks) in one launch
        {
            dim3 gg(enc_live ? 6 : 3, BB / 128);
            gemm_glu_kernel<DD, false><<<gg, 256, SMEM_BYTES>>>(
                p_ax, p_ax,
                p_eW0s + (size_t)s * HH * DD, p_dW0s + (size_t)s * HH * DD,
                eg0 + s * HH, eb0 + s * HH, dg0 + s * HH, db0 + s * HH,
                p_ase, p_asd, nullptr, nullptr, enc_live ? 3 : 0);
        }
        // GLU1: dec (block 0, u<64 -> final out) + enc (blocks 1,2 -> g_enc sigmoid)
        {
            dim3 gg(enc_live ? 3 : 1, BB / 128);
            gemm_glu_kernel<OUTF, true><<<gg, 256, SMEM_BYTES>>>(
                p_ase, p_asd,
                p_eW1s + (size_t)s * HH * OUTF, p_dW1s + (size_t)s * HH * OUTF,
                eg1 + s * HH, eb1 + s * HH, dg1 + s * HH, db1 + s * HH,
                nullptr, nullptr, p_enc, out + (size_t)s * BB * NDOUT, 0);
        }
    }
    if (out_size > BB * NDOUT * NSTEP) {
        loss_finalize_kernel<<<1, 256>>>(out + (size_t)BB * NDOUT * NSTEP);
    }
}

// round 9
// speedup vs baseline: 5.4915x; 1.0453x over previous
#include <cuda_runtime.h>
#include <cuda_fp16.h>
#include <cstdint>

// ---------------- problem constants ----------------
constexpr int BB     = 32768;   // batch
constexpr int DD     = 128;     // input dim
constexpr int OUTF   = 192;     // n_d + n_a
constexpr int HH     = 384;     // 2*OUTF
constexpr int NSTEP  = 3;
constexpr int NDOUT  = 64;      // n_d
constexpr int SMBLK  = 1024;    // sparsemax blocks (32 rows each)
#define EPS_BN 1e-5f

// ---------------- scratch (device globals: allocation-free) ----------------
__device__ float g_xbn[BB * DD];
__device__ float g_M[BB * DD];              // only written at step 1 (read at step 2)
__device__ float g_enc[BB * OUTF];          // sigmoid(enc GLU out); cols 64..191 used
__device__ float g_bnpart[256 * 2 * DD];
__device__ float g_bnscale[DD];
__device__ float g_bnshift[DD];
__device__ float g_losspart[NSTEP * SMBLK]; // only steps 1,2 written

// fp16 activations
__device__ __align__(128) __half g_ax[BB * DD];      // masked_x
__device__ __align__(128) __half g_ase[BB * OUTF];   // enc GLU0 out
__device__ __align__(128) __half g_asd[BB * OUTF];   // dec GLU0 out

// fp16 PERMUTED weights; row perm: n<192->2n else 2(n-192)+1
__device__ __align__(128) __half g_eW0s[NSTEP * HH * DD];
__device__ __align__(128) __half g_eW1s[NSTEP * HH * OUTF];
__device__ __align__(128) __half g_dW0s[NSTEP * HH * DD];
__device__ __align__(128) __half g_dW1s[NSTEP * HH * OUTF];

// ---------------- mma / ldmatrix / cp.async primitives ----------------
__device__ __forceinline__ void ldsm4(unsigned* r, const void* p) {
    unsigned a = (unsigned)__cvta_generic_to_shared(p);
    asm volatile("ldmatrix.sync.aligned.m8n8.x4.shared.b16 {%0,%1,%2,%3}, [%4];"
                 : "=r"(r[0]), "=r"(r[1]), "=r"(r[2]), "=r"(r[3]) : "r"(a));
}
__device__ __forceinline__ void mma16816(float* d, const unsigned* a, unsigned b0, unsigned b1) {
    asm volatile(
        "mma.sync.aligned.m16n8k16.row.col.f32.f16.f16.f32 "
        "{%0,%1,%2,%3}, {%4,%5,%6,%7}, {%8,%9}, {%0,%1,%2,%3};"
        : "+f"(d[0]), "+f"(d[1]), "+f"(d[2]), "+f"(d[3])
        : "r"(a[0]), "r"(a[1]), "r"(a[2]), "r"(a[3]), "r"(b0), "r"(b1));
}
__device__ __forceinline__ void cp16(void* sdst, const void* gsrc) {
    unsigned a = (unsigned)__cvta_generic_to_shared(sdst);
    asm volatile("cp.async.cg.shared.global [%0], [%1], 16;" :: "r"(a), "l"(gsrc));
}
__device__ __forceinline__ void cp_commit() {
    asm volatile("cp.async.commit_group;" ::: "memory");
}
__device__ __forceinline__ void cp_wait0() {
    asm volatile("cp.async.wait_group 0;" ::: "memory");
}

// ---------------- smem plan ----------
// mainloop: Asm/Bsm each [2][128][40] fp16 = 40960B total
// epilogue: partial sums p_s/p_q [4][128] fp32 + sc/sh [128] fp32 (separate region)
constexpr int SM_PS      = 40960;
constexpr int SM_PQ      = SM_PS + 2048;
constexpr int SM_SC_OFF  = SM_PQ + 2048;
constexpr int SM_SH_OFF  = SM_SC_OFF + 512;
constexpr int SMEM_BYTES = SM_SH_OFF + 512;   // 46080

// ---------------- BN stats ----------------
__global__ void bn_partial_kernel(const float* __restrict__ x) {
    __shared__ float ss[256], sq[256];
    int t = threadIdx.x, blk = blockIdx.x;
    int col = t & 127, half = t >> 7;
    const float* xp = x + ((size_t)blk * 128 + half * 64) * DD + col;
    float s = 0.f, q = 0.f;
#pragma unroll 8
    for (int r = 0; r < 64; r++) { float v = xp[(size_t)r * DD]; s += v; q += v * v; }
    ss[t] = s; sq[t] = q;
    __syncthreads();
    if (t < 128) {
        g_bnpart[(blk * 2 + 0) * DD + t] = ss[t] + ss[t + 128];
        g_bnpart[(blk * 2 + 1) * DD + t] = sq[t] + sq[t + 128];
    }
}

__global__ void bn_finalize_kernel(const float* __restrict__ gam, const float* __restrict__ bet) {
    int c = threadIdx.x;
    float s = 0.f, q = 0.f;
    for (int b = 0; b < 256; b++) {
        s += g_bnpart[(b * 2 + 0) * DD + c];
        q += g_bnpart[(b * 2 + 1) * DD + c];
    }
    float mean = s / (float)BB;
    float var  = q / (float)BB - mean * mean;
    float inv  = 1.f / sqrtf(var + EPS_BN);
    float sc   = gam[c] * inv;
    g_bnscale[c] = sc;
    g_bnshift[c] = bet[c] - mean * sc;
}

// BN apply + step-0 masked_x (M == 1/128 exactly when att == 1)
__global__ void bn_apply_kernel(const float* __restrict__ x) {
    int i = blockIdx.x * blockDim.x + threadIdx.x;
    if (i >= BB * DD / 4) return;
    float4 v = ((const float4*)x)[i];
    int c = (i & 31) * 4;
    v.x = v.x * g_bnscale[c + 0] + g_bnshift[c + 0];
    v.y = v.y * g_bnscale[c + 1] + g_bnshift[c + 1];
    v.z = v.z * g_bnscale[c + 2] + g_bnshift[c + 2];
    v.w = v.w * g_bnscale[c + 3] + g_bnshift[c + 3];
    ((float4*)g_xbn)[i] = v;
    const float m = 1.f / 128.f;
    __half2 h01 = __floats2half2_rn(v.x * m, v.y * m);
    __half2 h23 = __floats2half2_rn(v.z * m, v.w * m);
    ((uint2*)g_ax)[i] = make_uint2(*(unsigned*)&h01, *(unsigned*)&h23);
}

// ---------------- merged weight convert+permute (ONE launch, all 10) --------
__global__ void wsplit_all_kernel(const float* __restrict__ eW0, const float* __restrict__ eW1,
                                  const float* __restrict__ dW0, const float* __restrict__ dW1,
                                  __half* oe0, __half* oe1, __half* od0, __half* od1) {
    int y = blockIdx.y;
    int s = y >> 2, which = y & 3;
    if (s == NSTEP - 1 && which < 2) return;   // enc weights dead at last step
    int K = (which & 1) ? OUTF : DD;
    int i = blockIdx.x * 256 + threadIdx.x;
    if (i >= HH * K) return;
    const float* src = (which == 0 ? eW0 : which == 1 ? eW1 : which == 2 ? dW0 : dW1)
                       + (size_t)s * HH * K;
    __half* dst = (which == 0 ? oe0 : which == 1 ? oe1 : which == 2 ? od0 : od1)
                  + (size_t)s * HH * K;
    int n = i / K, k = i - n * K;
    int perm = (n < OUTF) ? (2 * n) : (2 * (n - OUTF) + 1);
    dst[(size_t)perm * K + k] = __float2half(src[i]);
}

// ---------------- sparsemax (steps 1,2 only) ----------------
__global__ void sparsemax_kernel(int step) {
    __shared__ float wl[8];
    int t = threadIdx.x, lane = t & 31, w = t >> 5, blk = blockIdx.x;
    float acc = 0.f;
    for (int rr = 0; rr < 4; rr++) {
        size_t row = (size_t)blk * 32 + w * 4 + rr;
        const float* xp = g_xbn + row * DD;
        float* Mp = g_M + row * DD;
        __half* axp = g_ax + row * DD;
        const float* ep = g_enc + row * OUTF + NDOUT;
        float z0, z1, z2, z3;
        if (step == 1) {   // previous M is the uniform constant 1/128
            const float om = 1.f - 1.f / 128.f;
            z0 = 1.3f * ep[lane]      * om;
            z1 = 1.3f * ep[lane + 32] * om;
            z2 = 1.3f * ep[lane + 64] * om;
            z3 = 1.3f * ep[lane + 96] * om;
        } else {
            z0 = 1.3f * ep[lane]      * (1.f - Mp[lane]);
            z1 = 1.3f * ep[lane + 32] * (1.f - Mp[lane + 32]);
            z2 = 1.3f * ep[lane + 64] * (1.f - Mp[lane + 64]);
            z3 = 1.3f * ep[lane + 96] * (1.f - Mp[lane + 96]);
        }
        float mx = fmaxf(fmaxf(z0, z1), fmaxf(z2, z3));
#pragma unroll
        for (int o = 16; o; o >>= 1) mx = fmaxf(mx, __shfl_xor_sync(0xffffffffu, mx, o));
        z0 -= mx; z1 -= mx; z2 -= mx; z3 -= mx;
        float sm = z0 + z1 + z2 + z3;
#pragma unroll
        for (int o = 16; o; o >>= 1) sm += __shfl_xor_sync(0xffffffffu, sm, o);
        float tau = (sm - 1.f) * (1.f / 128.f);
        int cnt = 128;
        for (int it = 0; it < 64; it++) {
            float s = 0.f; int c = 0;
            if (z0 > tau) { s += z0; c++; }
            if (z1 > tau) { s += z1; c++; }
            if (z2 > tau) { s += z2; c++; }
            if (z3 > tau) { s += z3; c++; }
#pragma unroll
            for (int o = 16; o; o >>= 1) {
                s += __shfl_xor_sync(0xffffffffu, s, o);
                c += __shfl_xor_sync(0xffffffffu, c, o);
            }
            if (c == cnt) break;
            cnt = c; tau = (s - 1.f) / (float)c;
        }
        float m[4] = {fmaxf(z0 - tau, 0.f), fmaxf(z1 - tau, 0.f),
                      fmaxf(z2 - tau, 0.f), fmaxf(z3 - tau, 0.f)};
        float rl = 0.f;
#pragma unroll
        for (int i = 0; i < 4; i++) {
            int c = lane + 32 * i;
            if (step < NSTEP - 1) Mp[c] = m[i];   // only needed by next step
            axp[c] = __float2half(m[i] * xp[c]);
            rl += m[i] * logf(m[i] + 1e-10f);
        }
#pragma unroll
        for (int o = 16; o; o >>= 1) rl += __shfl_xor_sync(0xffffffffu, rl, o);
        acc += rl;
    }
    if (lane == 0) wl[w] = acc;
    __syncthreads();
    if (t == 0) {
        float s = 0.f;
        for (int i = 0; i < 8; i++) s += wl[i];
        g_losspart[step * SMBLK + blk] = s;
    }
}

// ---------------- fused fp16 GEMM + GhostBN + GLU (register epilogue) --------
// GLU1=false: blockIdx.x < enc_blocks -> enc, else dec; fp16 activation write.
// GLU1=true : blockIdx.x == 0 -> dec (sigmoid -> f_out), else enc (sigmoid -> f_enc).
template <int K, bool GLU1>
__global__ __launch_bounds__(256, 2) void gemm_glu_kernel(
        const __half* __restrict__ Ae, const __half* __restrict__ Ad,
        const __half* __restrict__ We, const __half* __restrict__ Wd,
        const float* __restrict__ eg, const float* __restrict__ eb,
        const float* __restrict__ dg, const float* __restrict__ db,
        __half* __restrict__ h_oute, __half* __restrict__ h_outd,
        float* __restrict__ f_enc, float* __restrict__ f_out,
        int enc_blocks) {
    extern __shared__ __align__(16) char smem[];
    __half* Asm = (__half*)smem;              // [2][128][40]
    __half* Bsm = Asm + 2 * 128 * 40;
    constexpr int T = K / 32;

    const int t = threadIdx.x;
    const int m0 = blockIdx.y * 128;
    bool is_enc; int nx;
    if (GLU1) { is_enc = (blockIdx.x > 0); nx = blockIdx.x; }
    else      { is_enc = ((int)blockIdx.x < enc_blocks); nx = is_enc ? blockIdx.x : blockIdx.x - enc_blocks; }
    const int n0 = nx * 128;
    const __half* A = is_enc ? Ae : Ad;
    const __half* W = is_enc ? We : Wd;
    const float* gam = is_enc ? eg : dg;
    const float* bet = is_enc ? eb : db;

    const int lrow = t >> 1;
    const int lcol = (t & 1) * 16;
    const __half* Ag = A + (size_t)(m0 + lrow) * K + lcol;
    const __half* Wg = W + (size_t)(n0 + lrow) * K + lcol;

    const int warp = t >> 5, lane = t & 31;
    const int wm = warp >> 1, wn = warp & 1;
    const int lr = lane & 15, lc = (lane >> 4) * 8;
    const int so = lrow * 40 + lcol;

    float d[2][8][4];
#pragma unroll
    for (int i = 0; i < 2; i++)
#pragma unroll
        for (int j = 0; j < 8; j++)
#pragma unroll
            for (int k = 0; k < 4; k++) d[i][j][k] = 0.f;

    cp16(&Asm[so], Ag);  cp16(&Asm[so + 8], Ag + 8);
    cp16(&Bsm[so], Wg);  cp16(&Bsm[so + 8], Wg + 8);
    cp_commit(); cp_wait0();
    __syncthreads();

    for (int kt = 0; kt < T; kt++) {
        const int bo = (kt & 1) * 5120;
        if (kt + 1 < T) {
            const int no = ((kt + 1) & 1) * 5120, off = (kt + 1) * 32;
            cp16(&Asm[no + so], Ag + off);  cp16(&Asm[no + so + 8], Ag + off + 8);
            cp16(&Bsm[no + so], Wg + off);  cp16(&Bsm[no + so + 8], Wg + off + 8);
            cp_commit();
        }
#pragma unroll
        for (int ks = 0; ks < 2; ks++) {
            const int krow = ks * 16 + lc;
            unsigned afr[2][4], bfr[4][4];
#pragma unroll
            for (int mf = 0; mf < 2; mf++)
                ldsm4(afr[mf], &Asm[bo + (wm * 32 + mf * 16 + lr) * 40 + krow]);
#pragma unroll
            for (int nb = 0; nb < 4; nb++)
                ldsm4(bfr[nb], &Bsm[bo + (wn * 64 + nb * 16 + lr) * 40 + krow]);
#pragma unroll
            for (int mf = 0; mf < 2; mf++)
#pragma unroll
                for (int n8 = 0; n8 < 8; n8++)
                    mma16816(d[mf][n8], afr[mf], bfr[n8 >> 1][n8 & 1], bfr[n8 >> 1][(n8 & 1) + 2]);
        }
        if (kt + 1 < T) { cp_wait0(); __syncthreads(); }
    }

    // ---- register-resident GhostBN: per-column sums via shfl + tiny smem ----
    // Column cc = wn*64 + n8*8 + (lane&3)*2 (+parity). d[mf][n8][0/1]=rows r,r+ (cols cc,cc+1),
    // d[mf][n8][2/3]=rows+8. Reduce over lane>>2 (8 row-quads) with shfl_xor 4/8/16.
    float* p_s = (float*)(smem + SM_PS);   // [4 wm][128 cols]
    float* p_q = (float*)(smem + SM_PQ);
#pragma unroll
    for (int n8 = 0; n8 < 8; n8++) {
        float s0 = 0.f, s1 = 0.f, q0 = 0.f, q1 = 0.f;
#pragma unroll
        for (int mf = 0; mf < 2; mf++) {
            s0 += d[mf][n8][0] + d[mf][n8][2];
            s1 += d[mf][n8][1] + d[mf][n8][3];
            q0 += d[mf][n8][0] * d[mf][n8][0] + d[mf][n8][2] * d[mf][n8][2];
            q1 += d[mf][n8][1] * d[mf][n8][1] + d[mf][n8][3] * d[mf][n8][3];
        }
#pragma unroll
        for (int o = 4; o <= 16; o <<= 1) {
            s0 += __shfl_xor_sync(0xffffffffu, s0, o);
            s1 += __shfl_xor_sync(0xffffffffu, s1, o);
            q0 += __shfl_xor_sync(0xffffffffu, q0, o);
            q1 += __shfl_xor_sync(0xffffffffu, q1, o);
        }
        if (lane < 4) {
            int cc = wn * 64 + n8 * 8 + lane * 2;
            p_s[wm * 128 + cc]     = s0;  p_s[wm * 128 + cc + 1] = s1;
            p_q[wm * 128 + cc]     = q0;  p_q[wm * 128 + cc + 1] = q1;
        }
    }
    __syncthreads();

    float* scp = (float*)(smem + SM_SC_OFF);
    float* shp = (float*)(smem + SM_SH_OFF);
    if (t < 128) {
        float s = p_s[t] + p_s[128 + t] + p_s[256 + t] + p_s[384 + t];
        float q = p_q[t] + p_q[128 + t] + p_q[256 + t] + p_q[384 + t];
        float mean = s * (1.f / 128.f);
        float var  = q * (1.f / 128.f) - mean * mean;
        int ncol = n0 + t;
        int u = ncol >> 1, p = ncol & 1;
        int orig = u + p * OUTF;
        float scale = gam[orig] / sqrtf(var + EPS_BN);
        scp[t] = scale;
        shp[t] = bet[orig] - mean * scale;
    }
    __syncthreads();

    // ---- apply BN + GLU straight from accumulators ----
#pragma unroll
    for (int n8 = 0; n8 < 8; n8++) {
        int cc = wn * 64 + n8 * 8 + (lane & 3) * 2;
        float sa = scp[cc], ba = shp[cc], sg = scp[cc + 1], bg = shp[cc + 1];
        int u = nx * 64 + (cc >> 1);
#pragma unroll
        for (int mf = 0; mf < 2; mf++) {
            int r0 = m0 + wm * 32 + mf * 16 + (lane >> 2);
#pragma unroll
            for (int h = 0; h < 2; h++) {   // rows r0, r0+8
                float a = d[mf][n8][2 * h]     * sa + ba;
                float g = d[mf][n8][2 * h + 1] * sg + bg;
                float v = a * (1.f / (1.f + expf(-g)));
                size_t row = (size_t)(r0 + 8 * h);
                if (!GLU1) {
                    (is_enc ? h_oute : h_outd)[row * OUTF + u] = __float2half(v);
                } else {
                    float sig = 1.f / (1.f + expf(-v));
                    if (is_enc) f_enc[row * OUTF + u] = sig;
                    else        f_out[row * NDOUT + u] = sig;
                }
            }
        }
    }
}

// ---------------- loss finalize (adds analytic step-0 term) ----------------
__global__ void loss_finalize_kernel(float* __restrict__ outp) {
    __shared__ float s[256];
    int t = threadIdx.x;
    float a = 0.f;
    for (int i = t; i < 2 * SMBLK; i += 256) a += g_losspart[SMBLK + i];
    s[t] = a;
    __syncthreads();
    for (int o = 128; o; o >>= 1) {
        if (t < o) s[t] += s[t + o];
        __syncthreads();
    }
    if (t == 0) {
        float step0 = (float)BB * logf(1.f / 128.f + 1e-10f);   // uniform-M row loss
        outp[0] = (s[0] + step0) / ((float)BB * (float)NSTEP);
    }
}

// ---------------- launch ----------------
extern "C" void kernel_launch(void* const* d_in, const int* in_sizes, int n_in,
                              void* d_out, int out_size) {
    (void)in_sizes; (void)n_in;
    const float* x   = (const float*)d_in[0];
    const float* ig  = (const float*)d_in[1];
    const float* ib  = (const float*)d_in[2];
    const float* eW0 = (const float*)d_in[3];
    const float* eg0 = (const float*)d_in[4];
    const float* eb0 = (const float*)d_in[5];
    const float* eW1 = (const float*)d_in[6];
    const float* eg1 = (const float*)d_in[7];
    const float* eb1 = (const float*)d_in[8];
    const float* dW0 = (const float*)d_in[9];
    const float* dg0 = (const float*)d_in[10];
    const float* db0 = (const float*)d_in[11];
    const float* dW1 = (const float*)d_in[12];
    const float* dg1 = (const float*)d_in[13];
    const float* db1 = (const float*)d_in[14];
    float* out = (float*)d_out;

    float* p_enc;
    __half *p_ax, *p_ase, *p_asd, *p_eW0s, *p_eW1s, *p_dW0s, *p_dW1s;
    cudaGetSymbolAddress((void**)&p_enc, g_enc);
    cudaGetSymbolAddress((void**)&p_ax, g_ax);
    cudaGetSymbolAddress((void**)&p_ase, g_ase);
    cudaGetSymbolAddress((void**)&p_asd, g_asd);
    cudaGetSymbolAddress((void**)&p_eW0s, g_eW0s);
    cudaGetSymbolAddress((void**)&p_eW1s, g_eW1s);
    cudaGetSymbolAddress((void**)&p_dW0s, g_dW0s);
    cudaGetSymbolAddress((void**)&p_dW1s, g_dW1s);

    cudaFuncSetAttribute(gemm_glu_kernel<DD, false>,
                         cudaFuncAttributeMaxDynamicSharedMemorySize, SMEM_BYTES);
    cudaFuncSetAttribute(gemm_glu_kernel<OUTF, true>,
                         cudaFuncAttributeMaxDynamicSharedMemorySize, SMEM_BYTES);

    bn_partial_kernel<<<256, 256>>>(x);
    bn_finalize_kernel<<<1, DD>>>(ig, ib);
    bn_apply_kernel<<<BB * DD / 4 / 256, 256>>>(x);   // also emits step-0 masked_x fp16

    {
        dim3 gw((HH * OUTF + 255) / 256, NSTEP * 4);
        wsplit_all_kernel<<<gw, 256>>>(eW0, eW1, dW0, dW1, p_eW0s, p_eW1s, p_dW0s, p_dW1s);
    }

    for (int s = 0; s < NSTEP; s++) {
        if (s > 0) sparsemax_kernel<<<SMBLK, 256>>>(s);   // step 0 folded into bn_apply
        const bool enc_live = (s < NSTEP - 1);
        {
            dim3 gg(enc_live ? 6 : 3, BB / 128);
            gemm_glu_kernel<DD, false><<<gg, 256, SMEM_BYTES>>>(
                p_ax, p_ax,
                p_eW0s + (size_t)s * HH * DD, p_dW0s + (size_t)s * HH * DD,
                eg0 + s * HH, eb0 + s * HH, dg0 + s * HH, db0 + s * HH,
                p_ase, p_asd, nullptr, nullptr, enc_live ? 3 : 0);
        }
        {
            dim3 gg(enc_live ? 3 : 1, BB / 128);
            gemm_glu_kernel<OUTF, true><<<gg, 256, SMEM_BYTES>>>(
                p_ase, p_asd,
                p_eW1s + (size_t)s * HH * OUTF, p_dW1s + (size_t)s * HH * OUTF,
                eg1 + s * HH, eb1 + s * HH, dg1 + s * HH, db1 + s * HH,
                nullptr, nullptr, p_enc, out + (size_t)s * BB * NDOUT, 0);
        }
    }
    if (out_size > BB * NDOUT * NSTEP) {
        loss_finalize_kernel<<<1, 256>>>(out + (size_t)BB * NDOUT * NSTEP);
    }
}